// round 1
// baseline (speedup 1.0000x reference)
#include <cuda_runtime.h>
#include <cuda_bf16.h>
#include <math.h>

// ---------------------------------------------------------------------------
// DiT block, fp32 baseline.
// B=8, N=1024, M=128, C=1024, H=16, D=64, MLP=4096
// ---------------------------------------------------------------------------

#define Bc  8
#define Nn  1024
#define Mm  128
#define Cc  1024
#define Hh  16
#define Dd  64
#define MLPD 4096
#define ROWS (Bc * Nn)          // 8192

// ------------------------- scratch (device globals) ------------------------
__device__ float g_ada[Bc * 6 * Cc];          // (8, 6144)
__device__ float g_h[ROWS * Cc];              // modulated LN output
__device__ float g_qkv[ROWS * 3 * Cc];        // qkv (also reused for CA q)
__device__ float g_kv[Bc * Mm * 2 * Cc];      // (1024, 2048)
__device__ float g_attn[ROWS * Cc];           // attention output
__device__ float g_x1[ROWS * Cc];             // x after SA
__device__ float g_x2[ROWS * Cc];             // x after CA
__device__ float g_mlp[ROWS * MLPD];          // fc1 output

// ------------------------------ helpers ------------------------------------
__device__ __forceinline__ float gelu_tanh(float x) {
    float x3 = x * x * x;
    return 0.5f * x * (1.0f + tanhf(0.7978845608028654f * (x + 0.044715f * x3)));
}

__device__ __forceinline__ float block_sum_1024(float v) {
    __shared__ float red[8];
    __shared__ float bcast;
    int lane = threadIdx.x & 31, wid = threadIdx.x >> 5;
    #pragma unroll
    for (int o = 16; o; o >>= 1) v += __shfl_xor_sync(0xffffffffu, v, o);
    __syncthreads();               // protect red[] from a previous call
    if (lane == 0) red[wid] = v;
    __syncthreads();
    if (threadIdx.x == 0) {
        float t = 0.f;
        #pragma unroll
        for (int i = 0; i < 8; i++) t += red[i];
        bcast = t;
    }
    __syncthreads();
    return bcast;
}

// ----------------------- ada = silu(c_dino) @ W_ada + b --------------------
// grid (24, 8), 256 threads
__global__ __launch_bounds__(256) void ada_kernel(
    const float* __restrict__ cdino, const float* __restrict__ W,
    const float* __restrict__ bvec, float* __restrict__ out)
{
    __shared__ float s[Cc];
    int b = blockIdx.y, tid = threadIdx.x;
    for (int i = tid; i < Cc; i += 256) {
        float v = cdino[b * Cc + i];
        s[i] = v / (1.0f + __expf(-v));
    }
    __syncthreads();
    int n = blockIdx.x * 256 + tid;
    float acc = 0.f;
    #pragma unroll 4
    for (int k = 0; k < Cc; k++)
        acc = fmaf(s[k], W[(size_t)k * (6 * Cc) + n], acc);
    out[b * 6 * Cc + n] = acc + bvec[n];
}

// -------------------- h = modulate(ln(x), shift, scale) --------------------
// grid 8192 blocks, 256 threads; each thread owns 4 contiguous channels
__global__ __launch_bounds__(256) void lnmod_kernel(
    const float* __restrict__ X, const float* __restrict__ ada,
    int shiftOff, float* __restrict__ Hout)
{
    int row = blockIdx.x;
    int b = row >> 10;
    const float* xr = X + (size_t)row * Cc;
    int c = threadIdx.x * 4;

    float4 v = *(const float4*)(xr + c);
    float mu = block_sum_1024(v.x + v.y + v.z + v.w) * (1.0f / Cc);
    float c0 = v.x - mu, c1 = v.y - mu, c2 = v.z - mu, c3 = v.w - mu;
    float var = block_sum_1024(c0*c0 + c1*c1 + c2*c2 + c3*c3) * (1.0f / Cc);
    float rstd = rsqrtf(var + 1e-6f);

    const float* sh = ada + b * 6 * Cc + shiftOff;
    const float* sc = sh + Cc;
    float4 shv = *(const float4*)(sh + c);
    float4 scv = *(const float4*)(sc + c);
    float4 o;
    o.x = c0 * rstd * (1.0f + scv.x) + shv.x;
    o.y = c1 * rstd * (1.0f + scv.y) + shv.y;
    o.z = c2 * rstd * (1.0f + scv.z) + shv.z;
    o.w = c3 * rstd * (1.0f + scv.w) + shv.w;
    *(float4*)(Hout + (size_t)row * Cc + c) = o;
}

// ------------------------------- GEMM --------------------------------------
// C[M,N] = act(A[M,K] @ B[K,N] + bias) + residual
// BM=BN=128, BK=16, 256 threads, 8x8 per thread.  All dims multiples of tile.
#define GBM 128
#define GBN 128
#define GBK 16
__global__ __launch_bounds__(256) void gemm_kernel(
    const float* __restrict__ A, const float* __restrict__ B,
    const float* __restrict__ bias, const float* __restrict__ res,
    float* __restrict__ C, int M, int N, int K, int act)
{
    __shared__ float As[GBK][GBM];
    __shared__ float Bs[GBK][GBN];

    const int tid = threadIdx.x;
    const int tx = tid & 15, ty = tid >> 4;
    const int row0 = blockIdx.y * GBM, col0 = blockIdx.x * GBN;

    const float* Aptr = A + (size_t)row0 * K;
    const float* Bptr = B + col0;

    const int tA0 = tid, tA1 = tid + 256;       // 512 float4 of A tile
    const int ar0 = tA0 >> 2, ac0 = (tA0 & 3) << 2;
    const int ar1 = tA1 >> 2, ac1 = (tA1 & 3) << 2;
    const int br0 = tA0 >> 5, bc0 = (tA0 & 31) << 2;
    const int br1 = tA1 >> 5, bc1 = (tA1 & 31) << 2;

    // ---- preload tile 0 ----
    {
        float4 a0 = *(const float4*)(Aptr + (size_t)ar0 * K + ac0);
        float4 a1 = *(const float4*)(Aptr + (size_t)ar1 * K + ac1);
        float4 b0 = *(const float4*)(Bptr + (size_t)br0 * N + bc0);
        float4 b1 = *(const float4*)(Bptr + (size_t)br1 * N + bc1);
        As[ac0+0][ar0]=a0.x; As[ac0+1][ar0]=a0.y; As[ac0+2][ar0]=a0.z; As[ac0+3][ar0]=a0.w;
        As[ac1+0][ar1]=a1.x; As[ac1+1][ar1]=a1.y; As[ac1+2][ar1]=a1.z; As[ac1+3][ar1]=a1.w;
        *(float4*)&Bs[br0][bc0] = b0;
        *(float4*)&Bs[br1][bc1] = b1;
    }
    __syncthreads();

    float acc[8][8];
    #pragma unroll
    for (int i = 0; i < 8; i++)
        #pragma unroll
        for (int j = 0; j < 8; j++) acc[i][j] = 0.f;

    for (int kt = 0; kt < K; kt += GBK) {
        const bool has = (kt + GBK) < K;
        float4 na0, na1, nb0, nb1;
        if (has) {
            int k2 = kt + GBK;
            na0 = *(const float4*)(Aptr + (size_t)ar0 * K + k2 + ac0);
            na1 = *(const float4*)(Aptr + (size_t)ar1 * K + k2 + ac1);
            nb0 = *(const float4*)(Bptr + (size_t)(k2 + br0) * N + bc0);
            nb1 = *(const float4*)(Bptr + (size_t)(k2 + br1) * N + bc1);
        }
        #pragma unroll
        for (int k = 0; k < GBK; k++) {
            float a[8], b[8];
            *(float4*)&a[0] = *(const float4*)&As[k][ty*8];
            *(float4*)&a[4] = *(const float4*)&As[k][ty*8 + 4];
            *(float4*)&b[0] = *(const float4*)&Bs[k][tx*8];
            *(float4*)&b[4] = *(const float4*)&Bs[k][tx*8 + 4];
            #pragma unroll
            for (int i = 0; i < 8; i++)
                #pragma unroll
                for (int j = 0; j < 8; j++)
                    acc[i][j] = fmaf(a[i], b[j], acc[i][j]);
        }
        if (has) {
            __syncthreads();
            As[ac0+0][ar0]=na0.x; As[ac0+1][ar0]=na0.y; As[ac0+2][ar0]=na0.z; As[ac0+3][ar0]=na0.w;
            As[ac1+0][ar1]=na1.x; As[ac1+1][ar1]=na1.y; As[ac1+2][ar1]=na1.z; As[ac1+3][ar1]=na1.w;
            *(float4*)&Bs[br0][bc0] = nb0;
            *(float4*)&Bs[br1][bc1] = nb1;
            __syncthreads();
        }
    }

    // ---- epilogue: bias (+gelu) (+residual) ----
    #pragma unroll
    for (int i = 0; i < 8; i++) {
        int grow = row0 + ty*8 + i;
        #pragma unroll
        for (int j4 = 0; j4 < 8; j4 += 4) {
            int gcol = col0 + tx*8 + j4;
            float4 bv = *(const float4*)(bias + gcol);
            float4 o;
            o.x = acc[i][j4+0] + bv.x;
            o.y = acc[i][j4+1] + bv.y;
            o.z = acc[i][j4+2] + bv.z;
            o.w = acc[i][j4+3] + bv.w;
            if (act == 1) {
                o.x = gelu_tanh(o.x); o.y = gelu_tanh(o.y);
                o.z = gelu_tanh(o.z); o.w = gelu_tanh(o.w);
            }
            if (res) {
                float4 rv = *(const float4*)(res + (size_t)grow * N + gcol);
                o.x += rv.x; o.y += rv.y; o.z += rv.z; o.w += rv.w;
            }
            *(float4*)(C + (size_t)grow * N + gcol) = o;
        }
    }
}

// ---------------------------- flash attention ------------------------------
// grid (N/64, H, B), 256 threads; 64 queries x Lk keys, D=64, online softmax.
// Q row n:  Qp + (b*N + n)*qStride + h*64
// K/V row m: Kp/Vp + (b*Lk + m)*kvStride + h*64
// Output (B,N,C) row-major at head offset h*64.
__global__ __launch_bounds__(256) void attn_kernel(
    const float* __restrict__ Qp, const float* __restrict__ Kp,
    const float* __restrict__ Vp, float* __restrict__ Op,
    const int* __restrict__ maskp,
    int qStride, int kvStride, int Lk, float scale)
{
    extern __shared__ float sm[];
    float* Qs  = sm;            // [64][64]  Qs[d][i]  (transposed)
    float* KV  = sm + 4096;     // K as [d][j], then V as [j][d]
    float* Ss  = sm + 8192;     // [64][64]
    float* fac = sm + 12288;    // [64]
    float* lsm = sm + 12352;    // [64]

    const int tid = threadIdx.x;
    const int b = blockIdx.z, h = blockIdx.y;
    const int n0 = blockIdx.x * 64;
    const int tx = tid & 15, ty = tid >> 4;        // 16x16 grid, 4x4 per thread
    const int rr = tid >> 2, c4 = tid & 3;         // softmax: 4 threads / row

    // load Q tile transposed
    const float* Qbase = Qp + ((size_t)b * Nn + n0) * qStride + h * Dd;
    for (int t = tid; t < 1024; t += 256) {
        int i = t >> 4, d4 = (t & 15) << 2;
        float4 v = *(const float4*)(Qbase + (size_t)i * qStride + d4);
        Qs[(d4+0)*64+i]=v.x; Qs[(d4+1)*64+i]=v.y; Qs[(d4+2)*64+i]=v.z; Qs[(d4+3)*64+i]=v.w;
    }

    float acc[4][4];
    #pragma unroll
    for (int i = 0; i < 4; i++)
        #pragma unroll
        for (int j = 0; j < 4; j++) acc[i][j] = 0.f;
    float m_r = -INFINITY, l_r = 0.f;

    const int nTiles = Lk >> 6;
    for (int kt = 0; kt < nTiles; kt++) {
        __syncthreads();   // prior tile's AV reads of KV/Ss are done
        const float* Kbase = Kp + ((size_t)b * Lk + kt * 64) * kvStride + h * Dd;
        for (int t = tid; t < 1024; t += 256) {
            int i = t >> 4, d4 = (t & 15) << 2;
            float4 v = *(const float4*)(Kbase + (size_t)i * kvStride + d4);
            KV[(d4+0)*64+i]=v.x; KV[(d4+1)*64+i]=v.y; KV[(d4+2)*64+i]=v.z; KV[(d4+3)*64+i]=v.w;
        }
        __syncthreads();

        // S = Q K^T (4x4 per thread)
        float s[4][4];
        #pragma unroll
        for (int i = 0; i < 4; i++)
            #pragma unroll
            for (int j = 0; j < 4; j++) s[i][j] = 0.f;
        #pragma unroll 16
        for (int d = 0; d < 64; d++) {
            float4 qa = *(const float4*)&Qs[d*64 + ty*4];
            float4 kb = *(const float4*)&KV[d*64 + tx*4];
            s[0][0]=fmaf(qa.x,kb.x,s[0][0]); s[0][1]=fmaf(qa.x,kb.y,s[0][1]); s[0][2]=fmaf(qa.x,kb.z,s[0][2]); s[0][3]=fmaf(qa.x,kb.w,s[0][3]);
            s[1][0]=fmaf(qa.y,kb.x,s[1][0]); s[1][1]=fmaf(qa.y,kb.y,s[1][1]); s[1][2]=fmaf(qa.y,kb.z,s[1][2]); s[1][3]=fmaf(qa.y,kb.w,s[1][3]);
            s[2][0]=fmaf(qa.z,kb.x,s[2][0]); s[2][1]=fmaf(qa.z,kb.y,s[2][1]); s[2][2]=fmaf(qa.z,kb.z,s[2][2]); s[2][3]=fmaf(qa.z,kb.w,s[2][3]);
            s[3][0]=fmaf(qa.w,kb.x,s[3][0]); s[3][1]=fmaf(qa.w,kb.y,s[3][1]); s[3][2]=fmaf(qa.w,kb.z,s[3][2]); s[3][3]=fmaf(qa.w,kb.w,s[3][3]);
        }
        // write scaled (+mask) scores
        float mk[4] = {0.f, 0.f, 0.f, 0.f};
        if (maskp) {
            int jg0 = kt * 64 + tx * 4;
            #pragma unroll
            for (int jj = 0; jj < 4; jj++)
                mk[jj] = maskp[b * Lk + jg0 + jj] ? 0.f : -INFINITY;
        }
        #pragma unroll
        for (int i = 0; i < 4; i++)
            #pragma unroll
            for (int jj = 0; jj < 4; jj++)
                Ss[(ty*4+i)*64 + tx*4+jj] = s[i][jj] * scale + mk[jj];
        __syncthreads();

        // load V over KV (async w.r.t. softmax math below)
        const float* Vbase = Vp + ((size_t)b * Lk + kt * 64) * kvStride + h * Dd;
        for (int t = tid; t < 1024; t += 256) {
            int i = t >> 4, d4 = (t & 15) << 2;
            *(float4*)&KV[i*64 + d4] = *(const float4*)(Vbase + (size_t)i * kvStride + d4);
        }

        // online softmax on Ss rows (4 lanes per row)
        float* srow = &Ss[rr*64 + c4*16];
        float lm = -INFINITY;
        #pragma unroll
        for (int jj = 0; jj < 16; jj++) lm = fmaxf(lm, srow[jj]);
        lm = fmaxf(lm, __shfl_xor_sync(0xffffffffu, lm, 1));
        lm = fmaxf(lm, __shfl_xor_sync(0xffffffffu, lm, 2));
        float mnew = fmaxf(m_r, lm);
        float corr = __expf(m_r - mnew);
        float ssum = 0.f;
        #pragma unroll
        for (int jj = 0; jj < 16; jj++) {
            float e = __expf(srow[jj] - mnew);
            srow[jj] = e;
            ssum += e;
        }
        ssum += __shfl_xor_sync(0xffffffffu, ssum, 1);
        ssum += __shfl_xor_sync(0xffffffffu, ssum, 2);
        l_r = l_r * corr + ssum;
        m_r = mnew;
        if (c4 == 0) fac[rr] = corr;
        __syncthreads();

        // O = O*corr + P @ V
        #pragma unroll
        for (int i = 0; i < 4; i++) {
            float f = fac[ty*4 + i];
            acc[i][0]*=f; acc[i][1]*=f; acc[i][2]*=f; acc[i][3]*=f;
        }
        #pragma unroll 8
        for (int j = 0; j < 64; j++) {
            float4 v = *(const float4*)&KV[j*64 + tx*4];
            #pragma unroll
            for (int i = 0; i < 4; i++) {
                float p = Ss[(ty*4+i)*64 + j];
                acc[i][0]=fmaf(p,v.x,acc[i][0]); acc[i][1]=fmaf(p,v.y,acc[i][1]);
                acc[i][2]=fmaf(p,v.z,acc[i][2]); acc[i][3]=fmaf(p,v.w,acc[i][3]);
            }
        }
    }

    if (c4 == 0) lsm[rr] = l_r;
    __syncthreads();

    float* Obase = Op + ((size_t)b * Nn + n0) * Cc + h * Dd;
    #pragma unroll
    for (int i = 0; i < 4; i++) {
        float inv = 1.0f / lsm[ty*4 + i];
        float4 o;
        o.x = acc[i][0]*inv; o.y = acc[i][1]*inv;
        o.z = acc[i][2]*inv; o.w = acc[i][3]*inv;
        *(float4*)(Obase + (size_t)(ty*4+i) * Cc + tx*4) = o;
    }
}

// ------------------------------- launch ------------------------------------
static float* sym_addr(const void* sym) {
    void* p = nullptr;
    cudaGetSymbolAddress(&p, sym);
    return (float*)p;
}

extern "C" void kernel_launch(void* const* d_in, const int* in_sizes, int n_in,
                              void* d_out, int out_size)
{
    const float* x        = (const float*)d_in[0];
    const float* c_dino   = (const float*)d_in[1];
    const float* c_text   = (const float*)d_in[2];
    const int*   mask     = (const int*)  d_in[3];
    const float* W_ada    = (const float*)d_in[4];
    const float* b_ada    = (const float*)d_in[5];
    const float* W_qkv    = (const float*)d_in[6];
    const float* b_qkv    = (const float*)d_in[7];
    const float* W_psa    = (const float*)d_in[8];
    const float* b_psa    = (const float*)d_in[9];
    const float* W_q      = (const float*)d_in[10];
    const float* b_q      = (const float*)d_in[11];
    const float* W_kv     = (const float*)d_in[12];
    const float* b_kv     = (const float*)d_in[13];
    const float* W_pca    = (const float*)d_in[14];
    const float* b_pca    = (const float*)d_in[15];
    const float* W_fc1    = (const float*)d_in[16];
    const float* b_fc1    = (const float*)d_in[17];
    const float* W_fc2    = (const float*)d_in[18];
    const float* b_fc2    = (const float*)d_in[19];
    float* out = (float*)d_out;

    float* ada  = sym_addr(g_ada);
    float* hbuf = sym_addr(g_h);
    float* qkv  = sym_addr(g_qkv);
    float* kv   = sym_addr(g_kv);
    float* attn = sym_addr(g_attn);
    float* x1   = sym_addr(g_x1);
    float* x2   = sym_addr(g_x2);
    float* mlp  = sym_addr(g_mlp);

    const int ATTN_SMEM = (12352 + 64) * sizeof(float);  // 49664 B
    cudaFuncSetAttribute(attn_kernel, cudaFuncAttributeMaxDynamicSharedMemorySize, ATTN_SMEM);

    // ada = silu(c_dino) @ W_ada + b_ada
    ada_kernel<<<dim3(24, Bc), 256>>>(c_dino, W_ada, b_ada, ada);

    // ---- self attention ----
    lnmod_kernel<<<ROWS, 256>>>(x, ada, 0, hbuf);
    gemm_kernel<<<dim3(3*Cc/GBN, ROWS/GBM), 256>>>(hbuf, W_qkv, b_qkv, nullptr, qkv,
                                                   ROWS, 3*Cc, Cc, 0);
    attn_kernel<<<dim3(Nn/64, Hh, Bc), 256, ATTN_SMEM>>>(
        qkv, qkv + Cc, qkv + 2*Cc, attn, nullptr, 3*Cc, 3*Cc, Nn, 0.125f);
    gemm_kernel<<<dim3(Cc/GBN, ROWS/GBM), 256>>>(attn, W_psa, b_psa, x, x1,
                                                 ROWS, Cc, Cc, 0);

    // ---- cross attention ----
    lnmod_kernel<<<ROWS, 256>>>(x1, ada, 2*Cc, hbuf);
    gemm_kernel<<<dim3(Cc/GBN, ROWS/GBM), 256>>>(hbuf, W_q, b_q, nullptr, qkv,
                                                 ROWS, Cc, Cc, 0);
    gemm_kernel<<<dim3(2*Cc/GBN, (Bc*Mm)/GBM), 256>>>(c_text, W_kv, b_kv, nullptr, kv,
                                                      Bc*Mm, 2*Cc, Cc, 0);
    attn_kernel<<<dim3(Nn/64, Hh, Bc), 256, ATTN_SMEM>>>(
        qkv, kv, kv + Cc, attn, mask, Cc, 2*Cc, Mm, 0.125f);
    gemm_kernel<<<dim3(Cc/GBN, ROWS/GBM), 256>>>(attn, W_pca, b_pca, x1, x2,
                                                 ROWS, Cc, Cc, 0);

    // ---- MLP ----
    lnmod_kernel<<<ROWS, 256>>>(x2, ada, 4*Cc, hbuf);
    gemm_kernel<<<dim3(MLPD/GBN, ROWS/GBM), 256>>>(hbuf, W_fc1, b_fc1, nullptr, mlp,
                                                   ROWS, MLPD, Cc, 1 /*gelu*/);
    gemm_kernel<<<dim3(Cc/GBN, ROWS/GBM), 256>>>(mlp, W_fc2, b_fc2, x2, out,
                                                 ROWS, Cc, MLPD, 0);
}

// round 3
// speedup vs baseline: 1.8581x; 1.8581x over previous
#include <cuda_runtime.h>
#include <cuda_bf16.h>
#include <math.h>
#include <stdint.h>

// ---------------------------------------------------------------------------
// DiT block. GEMMs via mma.sync bf16 (2-term split, fp32 accum).
// B=8, N=1024, M=128, C=1024, H=16, D=64, MLP=4096
// NOTE: harness PTX target is compute_103 (no 'a') -> tcgen05 unavailable;
// mma.sync/ldmatrix/cp.async are the tensor-core path that compiles.
// ---------------------------------------------------------------------------

#define Bc  8
#define Nn  1024
#define Mm  128
#define Cc  1024
#define Hh  16
#define Dd  64
#define MLPD 4096
#define ROWS (Bc * Nn)          // 8192

// ------------------------- scratch (device globals) ------------------------
__device__ float g_ada[Bc * 6 * Cc];
__device__ float g_h[ROWS * Cc];
__device__ float g_qkv[ROWS * 3 * Cc];
__device__ float g_kv[Bc * Mm * 2 * Cc];
__device__ float g_attn[ROWS * Cc];
__device__ float g_x1[ROWS * Cc];
__device__ float g_x2[ROWS * Cc];
__device__ float g_mlp[ROWS * MLPD];

// transposed + bf16-split weights: [N][K] hi/lo planes
__device__ __align__(16) __nv_bfloat16 g_wqkv_h[Cc * 3 * Cc], g_wqkv_l[Cc * 3 * Cc];
__device__ __align__(16) __nv_bfloat16 g_wpsa_h[Cc * Cc],     g_wpsa_l[Cc * Cc];
__device__ __align__(16) __nv_bfloat16 g_wq_h[Cc * Cc],       g_wq_l[Cc * Cc];
__device__ __align__(16) __nv_bfloat16 g_wkv_h[Cc * 2 * Cc],  g_wkv_l[Cc * 2 * Cc];
__device__ __align__(16) __nv_bfloat16 g_wpca_h[Cc * Cc],     g_wpca_l[Cc * Cc];
__device__ __align__(16) __nv_bfloat16 g_wfc1_h[Cc * MLPD],   g_wfc1_l[Cc * MLPD];
__device__ __align__(16) __nv_bfloat16 g_wfc2_h[MLPD * Cc],   g_wfc2_l[MLPD * Cc];

// ------------------------------ ptx helpers --------------------------------
__device__ __forceinline__ uint32_t smem_u32(const void* p) {
    uint32_t a;
    asm("{ .reg .u64 t; cvta.to.shared.u64 t, %1; cvt.u32.u64 %0, t; }" : "=r"(a) : "l"(p));
    return a;
}
__device__ __forceinline__ void ldsm_x4(uint32_t& r0, uint32_t& r1, uint32_t& r2,
                                        uint32_t& r3, uint32_t a) {
    asm volatile("ldmatrix.sync.aligned.m8n8.x4.shared.b16 {%0,%1,%2,%3}, [%4];"
                 : "=r"(r0), "=r"(r1), "=r"(r2), "=r"(r3) : "r"(a));
}
__device__ __forceinline__ void mma16816(float* d, const uint32_t* a, const uint32_t* b) {
    asm volatile(
        "mma.sync.aligned.m16n8k16.row.col.f32.bf16.bf16.f32 "
        "{%0,%1,%2,%3}, {%4,%5,%6,%7}, {%8,%9}, {%0,%1,%2,%3};"
        : "+f"(d[0]), "+f"(d[1]), "+f"(d[2]), "+f"(d[3])
        : "r"(a[0]), "r"(a[1]), "r"(a[2]), "r"(a[3]), "r"(b[0]), "r"(b[1]));
}
__device__ __forceinline__ void cp16(uint32_t dst, const void* src) {
    asm volatile("cp.async.cg.shared.global [%0], [%1], 16;" :: "r"(dst), "l"(src));
}
#define CP_COMMIT asm volatile("cp.async.commit_group;" ::: "memory")
#define CP_WAIT0  asm volatile("cp.async.wait_group 0;" ::: "memory")

// swizzled tile offset: 128 rows x 4 chunks of 16B (64B rows), conflict-free
__device__ __forceinline__ uint32_t toff(int r, int c) {
    return ((uint32_t)r << 6) + ((uint32_t)((c ^ (r >> 1)) & 3) << 4);
}

// ------------------------------ misc helpers -------------------------------
__device__ __forceinline__ float gelu_tanh(float x) {
    float x3 = x * x * x;
    return 0.5f * x * (1.0f + tanhf(0.7978845608028654f * (x + 0.044715f * x3)));
}
__device__ __forceinline__ float block_sum_1024(float v) {
    __shared__ float red[8];
    __shared__ float bcast;
    int lane = threadIdx.x & 31, wid = threadIdx.x >> 5;
    #pragma unroll
    for (int o = 16; o; o >>= 1) v += __shfl_xor_sync(0xffffffffu, v, o);
    __syncthreads();
    if (lane == 0) red[wid] = v;
    __syncthreads();
    if (threadIdx.x == 0) {
        float t = 0.f;
        #pragma unroll
        for (int i = 0; i < 8; i++) t += red[i];
        bcast = t;
    }
    __syncthreads();
    return bcast;
}
__device__ __forceinline__ uint32_t packbf(float x, float y) {
    __nv_bfloat16 a = __float2bfloat16(x), b = __float2bfloat16(y);
    return ((uint32_t)__bfloat16_as_ushort(b) << 16) | __bfloat16_as_ushort(a);
}

// -------------------- weight prep: W[K][N] -> Wt_hi/lo [N][K] ---------------
__global__ __launch_bounds__(256) void wprep_kernel(
    const float* __restrict__ W, __nv_bfloat16* __restrict__ Th,
    __nv_bfloat16* __restrict__ Tl, int K, int N)
{
    __shared__ float t[32][33];
    int n0 = blockIdx.x * 32, k0 = blockIdx.y * 32;
    int tx = threadIdx.x & 31, ty = threadIdx.x >> 5;
    #pragma unroll
    for (int i = 0; i < 32; i += 8)
        t[ty + i][tx] = W[(size_t)(k0 + ty + i) * N + n0 + tx];
    __syncthreads();
    #pragma unroll
    for (int i = 0; i < 32; i += 8) {
        float v = t[tx][ty + i];
        __nv_bfloat16 h = __float2bfloat16(v);
        __nv_bfloat16 l = __float2bfloat16(v - __bfloat162float(h));
        size_t o = (size_t)(n0 + ty + i) * K + k0 + tx;
        Th[o] = h; Tl[o] = l;
    }
}

// ----------------------- ada = silu(c_dino) @ W_ada + b --------------------
__global__ __launch_bounds__(256) void ada_kernel(
    const float* __restrict__ cdino, const float* __restrict__ W,
    const float* __restrict__ bvec, float* __restrict__ out)
{
    __shared__ float s[Cc];
    int b = blockIdx.y, tid = threadIdx.x;
    for (int i = tid; i < Cc; i += 256) {
        float v = cdino[b * Cc + i];
        s[i] = v / (1.0f + __expf(-v));
    }
    __syncthreads();
    int n = blockIdx.x * 256 + tid;
    float acc = 0.f;
    #pragma unroll 4
    for (int k = 0; k < Cc; k++)
        acc = fmaf(s[k], W[(size_t)k * (6 * Cc) + n], acc);
    out[b * 6 * Cc + n] = acc + bvec[n];
}

// -------------------- h = modulate(ln(x), shift, scale) --------------------
__global__ __launch_bounds__(256) void lnmod_kernel(
    const float* __restrict__ X, const float* __restrict__ ada,
    int shiftOff, float* __restrict__ Hout)
{
    int row = blockIdx.x;
    int b = row >> 10;
    const float* xr = X + (size_t)row * Cc;
    int c = threadIdx.x * 4;

    float4 v = *(const float4*)(xr + c);
    float mu = block_sum_1024(v.x + v.y + v.z + v.w) * (1.0f / Cc);
    float c0 = v.x - mu, c1 = v.y - mu, c2 = v.z - mu, c3 = v.w - mu;
    float var = block_sum_1024(c0*c0 + c1*c1 + c2*c2 + c3*c3) * (1.0f / Cc);
    float rstd = rsqrtf(var + 1e-6f);

    const float* sh = ada + b * 6 * Cc + shiftOff;
    const float* sc = sh + Cc;
    float4 shv = *(const float4*)(sh + c);
    float4 scv = *(const float4*)(sc + c);
    float4 o;
    o.x = c0 * rstd * (1.0f + scv.x) + shv.x;
    o.y = c1 * rstd * (1.0f + scv.y) + shv.y;
    o.z = c2 * rstd * (1.0f + scv.z) + shv.z;
    o.w = c3 * rstd * (1.0f + scv.w) + shv.w;
    *(float4*)(Hout + (size_t)row * Cc + c) = o;
}

// --------------------------- mma.sync GEMM ---------------------------------
// C[M,N] = act(A[M,K] @ Wt^T + bias) + res
// A fp32 (split in-kernel), Wt bf16 hi/lo [N][K]. Tile 128x128x32, 8 warps.
#define PL_AH 0
#define PL_AL 8192
#define PL_BH 16384
#define PL_BL 24576
#define MSTAGE 32768
#define MM_SMEM 65536
#define MBK 32

__global__ __launch_bounds__(256) void mm_gemm(
    const float* __restrict__ A, const __nv_bfloat16* __restrict__ Bhp,
    const __nv_bfloat16* __restrict__ Blp, const float* __restrict__ bias,
    const float* __restrict__ res, float* __restrict__ C,
    int N, int K, int act)
{
    extern __shared__ char smem[];
    uint32_t sb = smem_u32(smem);
    const int tid = threadIdx.x, lane = tid & 31, warp = tid >> 5;
    const int wm = warp >> 2, wn = warp & 3;          // 2 x 4 warp grid
    const int row0 = blockIdx.y * 128, col0 = blockIdx.x * 128;

    // loader coords: each thread owns row lr_, chunks cb_ and cb_+1
    const int lr_ = tid >> 1;
    const int cb_ = (tid & 1) * 2;
    const float* Ag = A + (size_t)(row0 + lr_) * K + cb_ * 8;
    const __nv_bfloat16* Bhg = Bhp + (size_t)(col0 + lr_) * K + cb_ * 8;
    const __nv_bfloat16* Blg = Blp + (size_t)(col0 + lr_) * K + cb_ * 8;
    const uint32_t sA0 = toff(lr_, cb_), sA1 = toff(lr_, cb_ + 1);

    float d[4][4][4];
    #pragma unroll
    for (int i = 0; i < 4; i++)
        #pragma unroll
        for (int j = 0; j < 4; j++) {
            d[i][j][0] = d[i][j][1] = d[i][j][2] = d[i][j][3] = 0.f;
        }

    // prologue: stage 0
    {
        uint32_t base = sb;
        cp16(base + PL_BH + sA0, Bhg);
        cp16(base + PL_BH + sA1, Bhg + 8);
        cp16(base + PL_BL + sA0, Blg);
        cp16(base + PL_BL + sA1, Blg + 8);
        CP_COMMIT;
        float4 a0 = *(const float4*)(Ag);
        float4 a1 = *(const float4*)(Ag + 4);
        float4 a2 = *(const float4*)(Ag + 8);
        float4 a3 = *(const float4*)(Ag + 12);
        uint4 h0, l0, h1, l1;
        h0.x = packbf(a0.x, a0.y); h0.y = packbf(a0.z, a0.w);
        h0.z = packbf(a1.x, a1.y); h0.w = packbf(a1.z, a1.w);
        l0.x = packbf(a0.x - __bfloat162float(__float2bfloat16(a0.x)),
                      a0.y - __bfloat162float(__float2bfloat16(a0.y)));
        l0.y = packbf(a0.z - __bfloat162float(__float2bfloat16(a0.z)),
                      a0.w - __bfloat162float(__float2bfloat16(a0.w)));
        l0.z = packbf(a1.x - __bfloat162float(__float2bfloat16(a1.x)),
                      a1.y - __bfloat162float(__float2bfloat16(a1.y)));
        l0.w = packbf(a1.z - __bfloat162float(__float2bfloat16(a1.z)),
                      a1.w - __bfloat162float(__float2bfloat16(a1.w)));
        h1.x = packbf(a2.x, a2.y); h1.y = packbf(a2.z, a2.w);
        h1.z = packbf(a3.x, a3.y); h1.w = packbf(a3.z, a3.w);
        l1.x = packbf(a2.x - __bfloat162float(__float2bfloat16(a2.x)),
                      a2.y - __bfloat162float(__float2bfloat16(a2.y)));
        l1.y = packbf(a2.z - __bfloat162float(__float2bfloat16(a2.z)),
                      a2.w - __bfloat162float(__float2bfloat16(a2.w)));
        l1.z = packbf(a3.x - __bfloat162float(__float2bfloat16(a3.x)),
                      a3.y - __bfloat162float(__float2bfloat16(a3.y)));
        l1.w = packbf(a3.z - __bfloat162float(__float2bfloat16(a3.z)),
                      a3.w - __bfloat162float(__float2bfloat16(a3.w)));
        *(uint4*)(smem + PL_AH + sA0) = h0;
        *(uint4*)(smem + PL_AL + sA0) = l0;
        *(uint4*)(smem + PL_AH + sA1) = h1;
        *(uint4*)(smem + PL_AL + sA1) = l1;
    }
    CP_WAIT0;
    __syncthreads();

    const int g = lane >> 3, lq = lane & 7;
    const int nk = K / MBK;

    for (int kt = 0; kt < nk; kt++) {
        const int st = kt & 1;
        const uint32_t base = sb + st * MSTAGE;
        char* nsm = smem + (st ^ 1) * MSTAGE;

        float4 a0, a1, a2, a3;
        if (kt + 1 < nk) {
            uint32_t nb = sb + (st ^ 1) * MSTAGE;
            const __nv_bfloat16* bh = Bhg + (kt + 1) * MBK;
            const __nv_bfloat16* bl = Blg + (kt + 1) * MBK;
            cp16(nb + PL_BH + sA0, bh);
            cp16(nb + PL_BH + sA1, bh + 8);
            cp16(nb + PL_BL + sA0, bl);
            cp16(nb + PL_BL + sA1, bl + 8);
            CP_COMMIT;
            const float* ap = Ag + (kt + 1) * MBK;
            a0 = *(const float4*)(ap);
            a1 = *(const float4*)(ap + 4);
            a2 = *(const float4*)(ap + 8);
            a3 = *(const float4*)(ap + 12);
        }

        #pragma unroll
        for (int ks = 0; ks < 2; ks++) {
            uint32_t ah[4][4], al[4][4], bh[4][2], bl[4][2];
            // A frags: x4 covers m16 x k16
            const int arow = ((g & 1) << 3) + lq;
            const int acol = 2 * ks + (g >> 1);
            #pragma unroll
            for (int mi = 0; mi < 4; mi++) {
                uint32_t o = toff(wm * 64 + mi * 16 + arow, acol);
                ldsm_x4(ah[mi][0], ah[mi][1], ah[mi][2], ah[mi][3], base + PL_AH + o);
                ldsm_x4(al[mi][0], al[mi][1], al[mi][2], al[mi][3], base + PL_AL + o);
            }
            // B frags: x4 covers n16 x k16 -> two n8 frags
            const int brow = ((g >> 1) << 3) + lq;
            const int bcol = 2 * ks + (g & 1);
            #pragma unroll
            for (int nh = 0; nh < 2; nh++) {
                uint32_t o = toff(wn * 32 + nh * 16 + brow, bcol);
                uint32_t t0, t1, t2, t3;
                ldsm_x4(t0, t1, t2, t3, base + PL_BH + o);
                bh[nh*2][0] = t0; bh[nh*2][1] = t1;
                bh[nh*2+1][0] = t2; bh[nh*2+1][1] = t3;
                ldsm_x4(t0, t1, t2, t3, base + PL_BL + o);
                bl[nh*2][0] = t0; bl[nh*2][1] = t1;
                bl[nh*2+1][0] = t2; bl[nh*2+1][1] = t3;
            }
            #pragma unroll
            for (int mi = 0; mi < 4; mi++)
                #pragma unroll
                for (int ni = 0; ni < 4; ni++) {
                    mma16816(d[mi][ni], ah[mi], bh[ni]);
                    mma16816(d[mi][ni], al[mi], bh[ni]);
                    mma16816(d[mi][ni], ah[mi], bl[ni]);
                }
        }

        if (kt + 1 < nk) {
            uint4 h0, l0, h1, l1;
            h0.x = packbf(a0.x, a0.y); h0.y = packbf(a0.z, a0.w);
            h0.z = packbf(a1.x, a1.y); h0.w = packbf(a1.z, a1.w);
            l0.x = packbf(a0.x - __bfloat162float(__float2bfloat16(a0.x)),
                          a0.y - __bfloat162float(__float2bfloat16(a0.y)));
            l0.y = packbf(a0.z - __bfloat162float(__float2bfloat16(a0.z)),
                          a0.w - __bfloat162float(__float2bfloat16(a0.w)));
            l0.z = packbf(a1.x - __bfloat162float(__float2bfloat16(a1.x)),
                          a1.y - __bfloat162float(__float2bfloat16(a1.y)));
            l0.w = packbf(a1.z - __bfloat162float(__float2bfloat16(a1.z)),
                          a1.w - __bfloat162float(__float2bfloat16(a1.w)));
            h1.x = packbf(a2.x, a2.y); h1.y = packbf(a2.z, a2.w);
            h1.z = packbf(a3.x, a3.y); h1.w = packbf(a3.z, a3.w);
            l1.x = packbf(a2.x - __bfloat162float(__float2bfloat16(a2.x)),
                          a2.y - __bfloat162float(__float2bfloat16(a2.y)));
            l1.y = packbf(a2.z - __bfloat162float(__float2bfloat16(a2.z)),
                          a2.w - __bfloat162float(__float2bfloat16(a2.w)));
            l1.z = packbf(a3.x - __bfloat162float(__float2bfloat16(a3.x)),
                          a3.y - __bfloat162float(__float2bfloat16(a3.y)));
            l1.w = packbf(a3.z - __bfloat162float(__float2bfloat16(a3.z)),
                          a3.w - __bfloat162float(__float2bfloat16(a3.w)));
            *(uint4*)(nsm + PL_AH + sA0) = h0;
            *(uint4*)(nsm + PL_AL + sA0) = l0;
            *(uint4*)(nsm + PL_AH + sA1) = h1;
            *(uint4*)(nsm + PL_AL + sA1) = l1;
            CP_WAIT0;
            __syncthreads();
        }
    }

    // epilogue: bias (+gelu) (+res)
    const int rr = lane >> 2, cc2 = (lane & 3) * 2;
    #pragma unroll
    for (int mi = 0; mi < 4; mi++) {
        #pragma unroll
        for (int ni = 0; ni < 4; ni++) {
            int r0g = row0 + wm * 64 + mi * 16 + rr;
            int cg  = col0 + wn * 32 + ni * 8 + cc2;
            float b0 = bias[cg], b1 = bias[cg + 1];
            #pragma unroll
            for (int hrow = 0; hrow < 2; hrow++) {
                int r = r0g + hrow * 8;
                float v0 = d[mi][ni][hrow * 2 + 0] + b0;
                float v1 = d[mi][ni][hrow * 2 + 1] + b1;
                if (act == 1) { v0 = gelu_tanh(v0); v1 = gelu_tanh(v1); }
                if (res) {
                    float2 rv = *(const float2*)(res + (size_t)r * N + cg);
                    v0 += rv.x; v1 += rv.y;
                }
                float2 o; o.x = v0; o.y = v1;
                *(float2*)(C + (size_t)r * N + cg) = o;
            }
        }
    }
}

// ---------------------------- flash attention ------------------------------
__global__ __launch_bounds__(256) void attn_kernel(
    const float* __restrict__ Qp, const float* __restrict__ Kp,
    const float* __restrict__ Vp, float* __restrict__ Op,
    const int* __restrict__ maskp,
    int qStride, int kvStride, int Lk, float scale)
{
    extern __shared__ float sm[];
    float* Qs  = sm;
    float* KV  = sm + 4096;
    float* Ss  = sm + 8192;
    float* fac = sm + 12288;
    float* lsm = sm + 12352;

    const int tid = threadIdx.x;
    const int b = blockIdx.z, h = blockIdx.y;
    const int n0 = blockIdx.x * 64;
    const int tx = tid & 15, ty = tid >> 4;
    const int rr = tid >> 2, c4 = tid & 3;

    const float* Qbase = Qp + ((size_t)b * Nn + n0) * qStride + h * Dd;
    for (int t = tid; t < 1024; t += 256) {
        int i = t >> 4, d4 = (t & 15) << 2;
        float4 v = *(const float4*)(Qbase + (size_t)i * qStride + d4);
        Qs[(d4+0)*64+i]=v.x; Qs[(d4+1)*64+i]=v.y; Qs[(d4+2)*64+i]=v.z; Qs[(d4+3)*64+i]=v.w;
    }

    float acc[4][4];
    #pragma unroll
    for (int i = 0; i < 4; i++)
        #pragma unroll
        for (int j = 0; j < 4; j++) acc[i][j] = 0.f;
    float m_r = -INFINITY, l_r = 0.f;

    const int nTiles = Lk >> 6;
    for (int kt = 0; kt < nTiles; kt++) {
        __syncthreads();
        const float* Kbase = Kp + ((size_t)b * Lk + kt * 64) * kvStride + h * Dd;
        for (int t = tid; t < 1024; t += 256) {
            int i = t >> 4, d4 = (t & 15) << 2;
            float4 v = *(const float4*)(Kbase + (size_t)i * kvStride + d4);
            KV[(d4+0)*64+i]=v.x; KV[(d4+1)*64+i]=v.y; KV[(d4+2)*64+i]=v.z; KV[(d4+3)*64+i]=v.w;
        }
        __syncthreads();

        float s[4][4];
        #pragma unroll
        for (int i = 0; i < 4; i++)
            #pragma unroll
            for (int j = 0; j < 4; j++) s[i][j] = 0.f;
        #pragma unroll 16
        for (int d = 0; d < 64; d++) {
            float4 qa = *(const float4*)&Qs[d*64 + ty*4];
            float4 kb = *(const float4*)&KV[d*64 + tx*4];
            s[0][0]=fmaf(qa.x,kb.x,s[0][0]); s[0][1]=fmaf(qa.x,kb.y,s[0][1]); s[0][2]=fmaf(qa.x,kb.z,s[0][2]); s[0][3]=fmaf(qa.x,kb.w,s[0][3]);
            s[1][0]=fmaf(qa.y,kb.x,s[1][0]); s[1][1]=fmaf(qa.y,kb.y,s[1][1]); s[1][2]=fmaf(qa.y,kb.z,s[1][2]); s[1][3]=fmaf(qa.y,kb.w,s[1][3]);
            s[2][0]=fmaf(qa.z,kb.x,s[2][0]); s[2][1]=fmaf(qa.z,kb.y,s[2][1]); s[2][2]=fmaf(qa.z,kb.z,s[2][2]); s[2][3]=fmaf(qa.z,kb.w,s[2][3]);
            s[3][0]=fmaf(qa.w,kb.x,s[3][0]); s[3][1]=fmaf(qa.w,kb.y,s[3][1]); s[3][2]=fmaf(qa.w,kb.z,s[3][2]); s[3][3]=fmaf(qa.w,kb.w,s[3][3]);
        }
        float mk[4] = {0.f, 0.f, 0.f, 0.f};
        if (maskp) {
            int jg0 = kt * 64 + tx * 4;
            #pragma unroll
            for (int jj = 0; jj < 4; jj++)
                mk[jj] = maskp[b * Lk + jg0 + jj] ? 0.f : -INFINITY;
        }
        #pragma unroll
        for (int i = 0; i < 4; i++)
            #pragma unroll
            for (int jj = 0; jj < 4; jj++)
                Ss[(ty*4+i)*64 + tx*4+jj] = s[i][jj] * scale + mk[jj];
        __syncthreads();

        const float* Vbase = Vp + ((size_t)b * Lk + kt * 64) * kvStride + h * Dd;
        for (int t = tid; t < 1024; t += 256) {
            int i = t >> 4, d4 = (t & 15) << 2;
            *(float4*)&KV[i*64 + d4] = *(const float4*)(Vbase + (size_t)i * kvStride + d4);
        }

        float* srow = &Ss[rr*64 + c4*16];
        float lm = -INFINITY;
        #pragma unroll
        for (int jj = 0; jj < 16; jj++) lm = fmaxf(lm, srow[jj]);
        lm = fmaxf(lm, __shfl_xor_sync(0xffffffffu, lm, 1));
        lm = fmaxf(lm, __shfl_xor_sync(0xffffffffu, lm, 2));
        float mnew = fmaxf(m_r, lm);
        float corr = __expf(m_r - mnew);
        float ssum = 0.f;
        #pragma unroll
        for (int jj = 0; jj < 16; jj++) {
            float e = __expf(srow[jj] - mnew);
            srow[jj] = e;
            ssum += e;
        }
        ssum += __shfl_xor_sync(0xffffffffu, ssum, 1);
        ssum += __shfl_xor_sync(0xffffffffu, ssum, 2);
        l_r = l_r * corr + ssum;
        m_r = mnew;
        if (c4 == 0) fac[rr] = corr;
        __syncthreads();

        #pragma unroll
        for (int i = 0; i < 4; i++) {
            float f = fac[ty*4 + i];
            acc[i][0]*=f; acc[i][1]*=f; acc[i][2]*=f; acc[i][3]*=f;
        }
        #pragma unroll 8
        for (int j = 0; j < 64; j++) {
            float4 v = *(const float4*)&KV[j*64 + tx*4];
            #pragma unroll
            for (int i = 0; i < 4; i++) {
                float p = Ss[(ty*4+i)*64 + j];
                acc[i][0]=fmaf(p,v.x,acc[i][0]); acc[i][1]=fmaf(p,v.y,acc[i][1]);
                acc[i][2]=fmaf(p,v.z,acc[i][2]); acc[i][3]=fmaf(p,v.w,acc[i][3]);
            }
        }
    }

    if (c4 == 0) lsm[rr] = l_r;
    __syncthreads();

    float* Obase = Op + ((size_t)b * Nn + n0) * Cc + h * Dd;
    #pragma unroll
    for (int i = 0; i < 4; i++) {
        float inv = 1.0f / lsm[ty*4 + i];
        float4 o;
        o.x = acc[i][0]*inv; o.y = acc[i][1]*inv;
        o.z = acc[i][2]*inv; o.w = acc[i][3]*inv;
        *(float4*)(Obase + (size_t)(ty*4+i) * Cc + tx*4) = o;
    }
}

// ------------------------------- launch ------------------------------------
static void* sym_addr(const void* sym) {
    void* p = nullptr;
    cudaGetSymbolAddress(&p, sym);
    return p;
}

extern "C" void kernel_launch(void* const* d_in, const int* in_sizes, int n_in,
                              void* d_out, int out_size)
{
    const float* x        = (const float*)d_in[0];
    const float* c_dino   = (const float*)d_in[1];
    const float* c_text   = (const float*)d_in[2];
    const int*   mask     = (const int*)  d_in[3];
    const float* W_ada    = (const float*)d_in[4];
    const float* b_ada    = (const float*)d_in[5];
    const float* W_qkv    = (const float*)d_in[6];
    const float* b_qkv    = (const float*)d_in[7];
    const float* W_psa    = (const float*)d_in[8];
    const float* b_psa    = (const float*)d_in[9];
    const float* W_q      = (const float*)d_in[10];
    const float* b_q      = (const float*)d_in[11];
    const float* W_kv     = (const float*)d_in[12];
    const float* b_kv     = (const float*)d_in[13];
    const float* W_pca    = (const float*)d_in[14];
    const float* b_pca    = (const float*)d_in[15];
    const float* W_fc1    = (const float*)d_in[16];
    const float* b_fc1    = (const float*)d_in[17];
    const float* W_fc2    = (const float*)d_in[18];
    const float* b_fc2    = (const float*)d_in[19];
    float* out = (float*)d_out;

    float* ada  = (float*)sym_addr(g_ada);
    float* hbuf = (float*)sym_addr(g_h);
    float* qkv  = (float*)sym_addr(g_qkv);
    float* kv   = (float*)sym_addr(g_kv);
    float* attn = (float*)sym_addr(g_attn);
    float* x1   = (float*)sym_addr(g_x1);
    float* x2   = (float*)sym_addr(g_x2);
    float* mlp  = (float*)sym_addr(g_mlp);

    __nv_bfloat16* wqkv_h = (__nv_bfloat16*)sym_addr(g_wqkv_h);
    __nv_bfloat16* wqkv_l = (__nv_bfloat16*)sym_addr(g_wqkv_l);
    __nv_bfloat16* wpsa_h = (__nv_bfloat16*)sym_addr(g_wpsa_h);
    __nv_bfloat16* wpsa_l = (__nv_bfloat16*)sym_addr(g_wpsa_l);
    __nv_bfloat16* wq_h   = (__nv_bfloat16*)sym_addr(g_wq_h);
    __nv_bfloat16* wq_l   = (__nv_bfloat16*)sym_addr(g_wq_l);
    __nv_bfloat16* wkv_h  = (__nv_bfloat16*)sym_addr(g_wkv_h);
    __nv_bfloat16* wkv_l  = (__nv_bfloat16*)sym_addr(g_wkv_l);
    __nv_bfloat16* wpca_h = (__nv_bfloat16*)sym_addr(g_wpca_h);
    __nv_bfloat16* wpca_l = (__nv_bfloat16*)sym_addr(g_wpca_l);
    __nv_bfloat16* wfc1_h = (__nv_bfloat16*)sym_addr(g_wfc1_h);
    __nv_bfloat16* wfc1_l = (__nv_bfloat16*)sym_addr(g_wfc1_l);
    __nv_bfloat16* wfc2_h = (__nv_bfloat16*)sym_addr(g_wfc2_h);
    __nv_bfloat16* wfc2_l = (__nv_bfloat16*)sym_addr(g_wfc2_l);

    const int ATTN_SMEM = (12352 + 64) * sizeof(float);
    cudaFuncSetAttribute(attn_kernel, cudaFuncAttributeMaxDynamicSharedMemorySize, ATTN_SMEM);
    cudaFuncSetAttribute(mm_gemm, cudaFuncAttributeMaxDynamicSharedMemorySize, MM_SMEM);

    // ---- weight prep (transpose + bf16 split) ----
    wprep_kernel<<<dim3(3*Cc/32, Cc/32), 256>>>(W_qkv, wqkv_h, wqkv_l, Cc, 3*Cc);
    wprep_kernel<<<dim3(Cc/32,   Cc/32), 256>>>(W_psa, wpsa_h, wpsa_l, Cc, Cc);
    wprep_kernel<<<dim3(Cc/32,   Cc/32), 256>>>(W_q,   wq_h,   wq_l,   Cc, Cc);
    wprep_kernel<<<dim3(2*Cc/32, Cc/32), 256>>>(W_kv,  wkv_h,  wkv_l,  Cc, 2*Cc);
    wprep_kernel<<<dim3(Cc/32,   Cc/32), 256>>>(W_pca, wpca_h, wpca_l, Cc, Cc);
    wprep_kernel<<<dim3(MLPD/32, Cc/32), 256>>>(W_fc1, wfc1_h, wfc1_l, Cc, MLPD);
    wprep_kernel<<<dim3(Cc/32, MLPD/32), 256>>>(W_fc2, wfc2_h, wfc2_l, MLPD, Cc);

    // ada
    ada_kernel<<<dim3(24, Bc), 256>>>(c_dino, W_ada, b_ada, ada);

    // ---- self attention ----
    lnmod_kernel<<<ROWS, 256>>>(x, ada, 0, hbuf);
    mm_gemm<<<dim3(3*Cc/128, ROWS/128), 256, MM_SMEM>>>(
        hbuf, wqkv_h, wqkv_l, b_qkv, nullptr, qkv, 3*Cc, Cc, 0);
    attn_kernel<<<dim3(Nn/64, Hh, Bc), 256, ATTN_SMEM>>>(
        qkv, qkv + Cc, qkv + 2*Cc, attn, nullptr, 3*Cc, 3*Cc, Nn, 0.125f);
    mm_gemm<<<dim3(Cc/128, ROWS/128), 256, MM_SMEM>>>(
        attn, wpsa_h, wpsa_l, b_psa, x, x1, Cc, Cc, 0);

    // ---- cross attention ----
    lnmod_kernel<<<ROWS, 256>>>(x1, ada, 2*Cc, hbuf);
    mm_gemm<<<dim3(Cc/128, ROWS/128), 256, MM_SMEM>>>(
        hbuf, wq_h, wq_l, b_q, nullptr, qkv, Cc, Cc, 0);
    mm_gemm<<<dim3(2*Cc/128, (Bc*Mm)/128), 256, MM_SMEM>>>(
        c_text, wkv_h, wkv_l, b_kv, nullptr, kv, 2*Cc, Cc, 0);
    attn_kernel<<<dim3(Nn/64, Hh, Bc), 256, ATTN_SMEM>>>(
        qkv, kv, kv + Cc, attn, mask, Cc, 2*Cc, Mm, 0.125f);
    mm_gemm<<<dim3(Cc/128, ROWS/128), 256, MM_SMEM>>>(
        attn, wpca_h, wpca_l, b_pca, x1, x2, Cc, Cc, 0);

    // ---- MLP ----
    lnmod_kernel<<<ROWS, 256>>>(x2, ada, 4*Cc, hbuf);
    mm_gemm<<<dim3(MLPD/128, ROWS/128), 256, MM_SMEM>>>(
        hbuf, wfc1_h, wfc1_l, b_fc1, nullptr, mlp, MLPD, Cc, 1);
    mm_gemm<<<dim3(Cc/128, ROWS/128), 256, MM_SMEM>>>(
        mlp, wfc2_h, wfc2_l, b_fc2, x2, out, Cc, MLPD, 0);
}

// round 4
// speedup vs baseline: 2.2782x; 1.2261x over previous
#include <cuda_runtime.h>
#include <cuda_bf16.h>
#include <math.h>
#include <stdint.h>

// ---------------------------------------------------------------------------
// DiT block. GEMMs + attention via mma.sync bf16 (multi-term split, fp32 acc).
// B=8, N=1024, M=128, C=1024, H=16, D=64, MLP=4096
// ---------------------------------------------------------------------------

#define Bc  8
#define Nn  1024
#define Mm  128
#define Cc  1024
#define Hh  16
#define Dd  64
#define MLPD 4096
#define ROWS (Bc * Nn)          // 8192

// ------------------------- scratch (device globals) ------------------------
__device__ float g_ada[Bc * 6 * Cc];
__device__ float g_h[ROWS * Cc];
__device__ float g_qkv[ROWS * 3 * Cc];
__device__ float g_kv[Bc * Mm * 2 * Cc];
__device__ float g_attn[ROWS * Cc];
__device__ float g_x1[ROWS * Cc];
__device__ float g_x2[ROWS * Cc];
__device__ float g_mlp[ROWS * MLPD];

// transposed + bf16-split weights: [N][K] hi/lo planes
__device__ __align__(16) __nv_bfloat16 g_wqkv_h[Cc * 3 * Cc], g_wqkv_l[Cc * 3 * Cc];
__device__ __align__(16) __nv_bfloat16 g_wpsa_h[Cc * Cc],     g_wpsa_l[Cc * Cc];
__device__ __align__(16) __nv_bfloat16 g_wq_h[Cc * Cc],       g_wq_l[Cc * Cc];
__device__ __align__(16) __nv_bfloat16 g_wkv_h[Cc * 2 * Cc],  g_wkv_l[Cc * 2 * Cc];
__device__ __align__(16) __nv_bfloat16 g_wpca_h[Cc * Cc],     g_wpca_l[Cc * Cc];
__device__ __align__(16) __nv_bfloat16 g_wfc1_h[Cc * MLPD],   g_wfc1_l[Cc * MLPD];
__device__ __align__(16) __nv_bfloat16 g_wfc2_h[MLPD * Cc],   g_wfc2_l[MLPD * Cc];

// ------------------------------ ptx helpers --------------------------------
__device__ __forceinline__ uint32_t smem_u32(const void* p) {
    uint32_t a;
    asm("{ .reg .u64 t; cvta.to.shared.u64 t, %1; cvt.u32.u64 %0, t; }" : "=r"(a) : "l"(p));
    return a;
}
__device__ __forceinline__ void ldsm_x4(uint32_t& r0, uint32_t& r1, uint32_t& r2,
                                        uint32_t& r3, uint32_t a) {
    asm volatile("ldmatrix.sync.aligned.m8n8.x4.shared.b16 {%0,%1,%2,%3}, [%4];"
                 : "=r"(r0), "=r"(r1), "=r"(r2), "=r"(r3) : "r"(a));
}
__device__ __forceinline__ void ldsm_x4t(uint32_t& r0, uint32_t& r1, uint32_t& r2,
                                         uint32_t& r3, uint32_t a) {
    asm volatile("ldmatrix.sync.aligned.m8n8.x4.trans.shared.b16 {%0,%1,%2,%3}, [%4];"
                 : "=r"(r0), "=r"(r1), "=r"(r2), "=r"(r3) : "r"(a));
}
__device__ __forceinline__ void mma16816(float* d, const uint32_t* a, const uint32_t* b) {
    asm volatile(
        "mma.sync.aligned.m16n8k16.row.col.f32.bf16.bf16.f32 "
        "{%0,%1,%2,%3}, {%4,%5,%6,%7}, {%8,%9}, {%0,%1,%2,%3};"
        : "+f"(d[0]), "+f"(d[1]), "+f"(d[2]), "+f"(d[3])
        : "r"(a[0]), "r"(a[1]), "r"(a[2]), "r"(a[3]), "r"(b[0]), "r"(b[1]));
}
__device__ __forceinline__ void cp16(uint32_t dst, const void* src) {
    asm volatile("cp.async.cg.shared.global [%0], [%1], 16;" :: "r"(dst), "l"(src));
}
#define CP_COMMIT asm volatile("cp.async.commit_group;" ::: "memory")
#define CP_WAIT0  asm volatile("cp.async.wait_group 0;" ::: "memory")

// GEMM tile swizzle: 64B rows (4 chunks of 16B)
__device__ __forceinline__ uint32_t toff(int r, int c) {
    return ((uint32_t)r << 6) + ((uint32_t)((c ^ (r >> 1)) & 3) << 4);
}
// attention tile swizzle: 128B rows (8 chunks of 16B), ldmatrix conflict-free
__device__ __forceinline__ uint32_t aoff(int r, int c) {
    return ((uint32_t)r << 7) + ((uint32_t)((c ^ (r & 7)) & 7) << 4);
}

// ------------------------------ misc helpers -------------------------------
__device__ __forceinline__ float gelu_tanh(float x) {
    float x3 = x * x * x;
    return 0.5f * x * (1.0f + tanhf(0.7978845608028654f * (x + 0.044715f * x3)));
}
__device__ __forceinline__ float block_sum_1024(float v) {
    __shared__ float red[8];
    __shared__ float bcast;
    int lane = threadIdx.x & 31, wid = threadIdx.x >> 5;
    #pragma unroll
    for (int o = 16; o; o >>= 1) v += __shfl_xor_sync(0xffffffffu, v, o);
    __syncthreads();
    if (lane == 0) red[wid] = v;
    __syncthreads();
    if (threadIdx.x == 0) {
        float t = 0.f;
        #pragma unroll
        for (int i = 0; i < 8; i++) t += red[i];
        bcast = t;
    }
    __syncthreads();
    return bcast;
}
__device__ __forceinline__ uint32_t packbf(float x, float y) {
    __nv_bfloat16 a = __float2bfloat16(x), b = __float2bfloat16(y);
    return ((uint32_t)__bfloat16_as_ushort(b) << 16) | __bfloat16_as_ushort(a);
}
__device__ __forceinline__ float lobf(float x) {
    return x - __bfloat162float(__float2bfloat16(x));
}

// -------------------- weight prep: W[K][N] -> Wt_hi/lo [N][K] ---------------
__global__ __launch_bounds__(256) void wprep_kernel(
    const float* __restrict__ W, __nv_bfloat16* __restrict__ Th,
    __nv_bfloat16* __restrict__ Tl, int K, int N)
{
    __shared__ float t[32][33];
    int n0 = blockIdx.x * 32, k0 = blockIdx.y * 32;
    int tx = threadIdx.x & 31, ty = threadIdx.x >> 5;
    #pragma unroll
    for (int i = 0; i < 32; i += 8)
        t[ty + i][tx] = W[(size_t)(k0 + ty + i) * N + n0 + tx];
    __syncthreads();
    #pragma unroll
    for (int i = 0; i < 32; i += 8) {
        float v = t[tx][ty + i];
        __nv_bfloat16 h = __float2bfloat16(v);
        __nv_bfloat16 l = __float2bfloat16(v - __bfloat162float(h));
        size_t o = (size_t)(n0 + ty + i) * K + k0 + tx;
        Th[o] = h; Tl[o] = l;
    }
}

// ----------------------- ada = silu(c_dino) @ W_ada + b --------------------
__global__ __launch_bounds__(256) void ada_kernel(
    const float* __restrict__ cdino, const float* __restrict__ W,
    const float* __restrict__ bvec, float* __restrict__ out)
{
    __shared__ float s[Cc];
    int b = blockIdx.y, tid = threadIdx.x;
    for (int i = tid; i < Cc; i += 256) {
        float v = cdino[b * Cc + i];
        s[i] = v / (1.0f + __expf(-v));
    }
    __syncthreads();
    int n = blockIdx.x * 256 + tid;
    float acc = 0.f;
    #pragma unroll 4
    for (int k = 0; k < Cc; k++)
        acc = fmaf(s[k], W[(size_t)k * (6 * Cc) + n], acc);
    out[b * 6 * Cc + n] = acc + bvec[n];
}

// -------------------- h = modulate(ln(x), shift, scale) --------------------
__global__ __launch_bounds__(256) void lnmod_kernel(
    const float* __restrict__ X, const float* __restrict__ ada,
    int shiftOff, float* __restrict__ Hout)
{
    int row = blockIdx.x;
    int b = row >> 10;
    const float* xr = X + (size_t)row * Cc;
    int c = threadIdx.x * 4;

    float4 v = *(const float4*)(xr + c);
    float mu = block_sum_1024(v.x + v.y + v.z + v.w) * (1.0f / Cc);
    float c0 = v.x - mu, c1 = v.y - mu, c2 = v.z - mu, c3 = v.w - mu;
    float var = block_sum_1024(c0*c0 + c1*c1 + c2*c2 + c3*c3) * (1.0f / Cc);
    float rstd = rsqrtf(var + 1e-6f);

    const float* sh = ada + b * 6 * Cc + shiftOff;
    const float* sc = sh + Cc;
    float4 shv = *(const float4*)(sh + c);
    float4 scv = *(const float4*)(sc + c);
    float4 o;
    o.x = c0 * rstd * (1.0f + scv.x) + shv.x;
    o.y = c1 * rstd * (1.0f + scv.y) + shv.y;
    o.z = c2 * rstd * (1.0f + scv.z) + shv.z;
    o.w = c3 * rstd * (1.0f + scv.w) + shv.w;
    *(float4*)(Hout + (size_t)row * Cc + c) = o;
}

// --------------------------- mma.sync GEMM ---------------------------------
#define PL_AH 0
#define PL_AL 8192
#define PL_BH 16384
#define PL_BL 24576
#define MSTAGE 32768
#define MM_SMEM 65536
#define MBK 32

__global__ __launch_bounds__(256) void mm_gemm(
    const float* __restrict__ A, const __nv_bfloat16* __restrict__ Bhp,
    const __nv_bfloat16* __restrict__ Blp, const float* __restrict__ bias,
    const float* __restrict__ res, float* __restrict__ C,
    int N, int K, int act)
{
    extern __shared__ char smem[];
    uint32_t sb = smem_u32(smem);
    const int tid = threadIdx.x, lane = tid & 31, warp = tid >> 5;
    const int wm = warp >> 2, wn = warp & 3;
    const int row0 = blockIdx.y * 128, col0 = blockIdx.x * 128;

    const int lr_ = tid >> 1;
    const int cb_ = (tid & 1) * 2;
    const float* Ag = A + (size_t)(row0 + lr_) * K + cb_ * 8;
    const __nv_bfloat16* Bhg = Bhp + (size_t)(col0 + lr_) * K + cb_ * 8;
    const __nv_bfloat16* Blg = Blp + (size_t)(col0 + lr_) * K + cb_ * 8;
    const uint32_t sA0 = toff(lr_, cb_), sA1 = toff(lr_, cb_ + 1);

    float d[4][4][4];
    #pragma unroll
    for (int i = 0; i < 4; i++)
        #pragma unroll
        for (int j = 0; j < 4; j++) {
            d[i][j][0] = d[i][j][1] = d[i][j][2] = d[i][j][3] = 0.f;
        }

    {
        uint32_t base = sb;
        cp16(base + PL_BH + sA0, Bhg);
        cp16(base + PL_BH + sA1, Bhg + 8);
        cp16(base + PL_BL + sA0, Blg);
        cp16(base + PL_BL + sA1, Blg + 8);
        CP_COMMIT;
        float4 a0 = *(const float4*)(Ag);
        float4 a1 = *(const float4*)(Ag + 4);
        float4 a2 = *(const float4*)(Ag + 8);
        float4 a3 = *(const float4*)(Ag + 12);
        uint4 h0, l0, h1, l1;
        h0.x = packbf(a0.x, a0.y); h0.y = packbf(a0.z, a0.w);
        h0.z = packbf(a1.x, a1.y); h0.w = packbf(a1.z, a1.w);
        l0.x = packbf(lobf(a0.x), lobf(a0.y)); l0.y = packbf(lobf(a0.z), lobf(a0.w));
        l0.z = packbf(lobf(a1.x), lobf(a1.y)); l0.w = packbf(lobf(a1.z), lobf(a1.w));
        h1.x = packbf(a2.x, a2.y); h1.y = packbf(a2.z, a2.w);
        h1.z = packbf(a3.x, a3.y); h1.w = packbf(a3.z, a3.w);
        l1.x = packbf(lobf(a2.x), lobf(a2.y)); l1.y = packbf(lobf(a2.z), lobf(a2.w));
        l1.z = packbf(lobf(a3.x), lobf(a3.y)); l1.w = packbf(lobf(a3.z), lobf(a3.w));
        *(uint4*)(smem + PL_AH + sA0) = h0;
        *(uint4*)(smem + PL_AL + sA0) = l0;
        *(uint4*)(smem + PL_AH + sA1) = h1;
        *(uint4*)(smem + PL_AL + sA1) = l1;
    }
    CP_WAIT0;
    __syncthreads();

    const int g = lane >> 3, lq = lane & 7;
    const int nk = K / MBK;

    for (int kt = 0; kt < nk; kt++) {
        const int st = kt & 1;
        const uint32_t base = sb + st * MSTAGE;
        char* nsm = smem + (st ^ 1) * MSTAGE;

        float4 a0, a1, a2, a3;
        if (kt + 1 < nk) {
            uint32_t nb = sb + (st ^ 1) * MSTAGE;
            const __nv_bfloat16* bh = Bhg + (kt + 1) * MBK;
            const __nv_bfloat16* bl = Blg + (kt + 1) * MBK;
            cp16(nb + PL_BH + sA0, bh);
            cp16(nb + PL_BH + sA1, bh + 8);
            cp16(nb + PL_BL + sA0, bl);
            cp16(nb + PL_BL + sA1, bl + 8);
            CP_COMMIT;
            const float* ap = Ag + (kt + 1) * MBK;
            a0 = *(const float4*)(ap);
            a1 = *(const float4*)(ap + 4);
            a2 = *(const float4*)(ap + 8);
            a3 = *(const float4*)(ap + 12);
        }

        #pragma unroll
        for (int ks = 0; ks < 2; ks++) {
            uint32_t ah[4][4], al[4][4], bh[4][2], bl[4][2];
            const int arow = ((g & 1) << 3) + lq;
            const int acol = 2 * ks + (g >> 1);
            #pragma unroll
            for (int mi = 0; mi < 4; mi++) {
                uint32_t o = toff(wm * 64 + mi * 16 + arow, acol);
                ldsm_x4(ah[mi][0], ah[mi][1], ah[mi][2], ah[mi][3], base + PL_AH + o);
                ldsm_x4(al[mi][0], al[mi][1], al[mi][2], al[mi][3], base + PL_AL + o);
            }
            const int brow = ((g >> 1) << 3) + lq;
            const int bcol = 2 * ks + (g & 1);
            #pragma unroll
            for (int nh = 0; nh < 2; nh++) {
                uint32_t o = toff(wn * 32 + nh * 16 + brow, bcol);
                uint32_t t0, t1, t2, t3;
                ldsm_x4(t0, t1, t2, t3, base + PL_BH + o);
                bh[nh*2][0] = t0; bh[nh*2][1] = t1;
                bh[nh*2+1][0] = t2; bh[nh*2+1][1] = t3;
                ldsm_x4(t0, t1, t2, t3, base + PL_BL + o);
                bl[nh*2][0] = t0; bl[nh*2][1] = t1;
                bl[nh*2+1][0] = t2; bl[nh*2+1][1] = t3;
            }
            #pragma unroll
            for (int mi = 0; mi < 4; mi++)
                #pragma unroll
                for (int ni = 0; ni < 4; ni++) {
                    mma16816(d[mi][ni], ah[mi], bh[ni]);
                    mma16816(d[mi][ni], al[mi], bh[ni]);
                    mma16816(d[mi][ni], ah[mi], bl[ni]);
                }
        }

        if (kt + 1 < nk) {
            uint4 h0, l0, h1, l1;
            h0.x = packbf(a0.x, a0.y); h0.y = packbf(a0.z, a0.w);
            h0.z = packbf(a1.x, a1.y); h0.w = packbf(a1.z, a1.w);
            l0.x = packbf(lobf(a0.x), lobf(a0.y)); l0.y = packbf(lobf(a0.z), lobf(a0.w));
            l0.z = packbf(lobf(a1.x), lobf(a1.y)); l0.w = packbf(lobf(a1.z), lobf(a1.w));
            h1.x = packbf(a2.x, a2.y); h1.y = packbf(a2.z, a2.w);
            h1.z = packbf(a3.x, a3.y); h1.w = packbf(a3.z, a3.w);
            l1.x = packbf(lobf(a2.x), lobf(a2.y)); l1.y = packbf(lobf(a2.z), lobf(a2.w));
            l1.z = packbf(lobf(a3.x), lobf(a3.y)); l1.w = packbf(lobf(a3.z), lobf(a3.w));
            *(uint4*)(nsm + PL_AH + sA0) = h0;
            *(uint4*)(nsm + PL_AL + sA0) = l0;
            *(uint4*)(nsm + PL_AH + sA1) = h1;
            *(uint4*)(nsm + PL_AL + sA1) = l1;
            CP_WAIT0;
            __syncthreads();
        }
    }

    const int rr = lane >> 2, cc2 = (lane & 3) * 2;
    #pragma unroll
    for (int mi = 0; mi < 4; mi++) {
        #pragma unroll
        for (int ni = 0; ni < 4; ni++) {
            int r0g = row0 + wm * 64 + mi * 16 + rr;
            int cg  = col0 + wn * 32 + ni * 8 + cc2;
            float b0 = bias[cg], b1 = bias[cg + 1];
            #pragma unroll
            for (int hrow = 0; hrow < 2; hrow++) {
                int r = r0g + hrow * 8;
                float v0 = d[mi][ni][hrow * 2 + 0] + b0;
                float v1 = d[mi][ni][hrow * 2 + 1] + b1;
                if (act == 1) { v0 = gelu_tanh(v0); v1 = gelu_tanh(v1); }
                if (res) {
                    float2 rv = *(const float2*)(res + (size_t)r * N + cg);
                    v0 += rv.x; v1 += rv.y;
                }
                float2 o; o.x = v0; o.y = v1;
                *(float2*)(C + (size_t)r * N + cg) = o;
            }
        }
    }
}

// ------------------- tensor-core flash attention ---------------------------
// 4 warps, 64 q x 64 k tiles, D=64. bf16 hi/lo splits everywhere.
// smem: QH 0, QL 8192, KH 16384, KL 24576, VH 32768, VL 40960, MADD 49152
#define AT_QH 0
#define AT_QL 8192
#define AT_KH 16384
#define AT_KL 24576
#define AT_VH 32768
#define AT_VL 40960
#define AT_MD 49152
#define AT_SMEM 49408

__global__ __launch_bounds__(128) void attn_tc(
    const float* __restrict__ Qp, const float* __restrict__ Kp,
    const float* __restrict__ Vp, float* __restrict__ Op,
    const int* __restrict__ maskp,
    int qStride, int kvStride, int Lk, float scale)
{
    extern __shared__ char smem[];
    uint32_t sb = smem_u32(smem);
    const int tid = threadIdx.x, lane = tid & 31, warp = tid >> 5;
    const int b = blockIdx.z, h = blockIdx.y, n0 = blockIdx.x * 64;
    const int w16 = warp * 16;

    // ---- load Q (x scale), split into hi/lo planes ----
    {
        int r = tid >> 1, half = tid & 1;
        const float* qg = Qp + (size_t)(b * Nn + n0 + r) * qStride + h * Dd + half * 32;
        #pragma unroll
        for (int j = 0; j < 4; j++) {
            float4 a = *(const float4*)(qg + j * 8);
            float4 c = *(const float4*)(qg + j * 8 + 4);
            a.x *= scale; a.y *= scale; a.z *= scale; a.w *= scale;
            c.x *= scale; c.y *= scale; c.z *= scale; c.w *= scale;
            uint4 hh, ll;
            hh.x = packbf(a.x, a.y); hh.y = packbf(a.z, a.w);
            hh.z = packbf(c.x, c.y); hh.w = packbf(c.z, c.w);
            ll.x = packbf(lobf(a.x), lobf(a.y)); ll.y = packbf(lobf(a.z), lobf(a.w));
            ll.z = packbf(lobf(c.x), lobf(c.y)); ll.w = packbf(lobf(c.z), lobf(c.w));
            uint32_t o = aoff(r, half * 4 + j);
            *(uint4*)(smem + AT_QH + o) = hh;
            *(uint4*)(smem + AT_QL + o) = ll;
        }
    }
    __syncthreads();

    // ---- Q A-fragments (held in registers for the whole kernel) ----
    uint32_t qh[4][4], ql[4][4];
    {
        int rr = (lane & 7) + 8 * ((lane >> 3) & 1);
        int cc = lane >> 4;
        #pragma unroll
        for (int kc = 0; kc < 4; kc++) {
            uint32_t o = aoff(w16 + rr, kc * 2 + cc);
            ldsm_x4(qh[kc][0], qh[kc][1], qh[kc][2], qh[kc][3], sb + AT_QH + o);
            ldsm_x4(ql[kc][0], ql[kc][1], ql[kc][2], ql[kc][3], sb + AT_QL + o);
        }
    }

    float o_[8][4];
    #pragma unroll
    for (int i = 0; i < 8; i++) { o_[i][0]=o_[i][1]=o_[i][2]=o_[i][3]=0.f; }
    float m0 = -INFINITY, m1 = -INFINITY, l0 = 0.f, l1 = 0.f;

    const int krow = (lane & 7) + 8 * (lane >> 4);
    const int kcsel = (lane >> 3) & 1;
    const int vrow = lane & 15, vcsel = lane >> 4;
    const float* madd = (const float*)(smem + AT_MD);

    const int nTiles = Lk >> 6;
    for (int kt = 0; kt < nTiles; kt++) {
        __syncthreads();
        // ---- load K & V tiles, split ----
        {
            int r = tid >> 1, half = tid & 1;
            const float* kg = Kp + (size_t)(b * Lk + kt * 64 + r) * kvStride + h * Dd + half * 32;
            const float* vg = Vp + (size_t)(b * Lk + kt * 64 + r) * kvStride + h * Dd + half * 32;
            #pragma unroll
            for (int j = 0; j < 4; j++) {
                float4 a = *(const float4*)(kg + j * 8);
                float4 c = *(const float4*)(kg + j * 8 + 4);
                uint4 hh, ll;
                hh.x = packbf(a.x, a.y); hh.y = packbf(a.z, a.w);
                hh.z = packbf(c.x, c.y); hh.w = packbf(c.z, c.w);
                ll.x = packbf(lobf(a.x), lobf(a.y)); ll.y = packbf(lobf(a.z), lobf(a.w));
                ll.z = packbf(lobf(c.x), lobf(c.y)); ll.w = packbf(lobf(c.z), lobf(c.w));
                uint32_t o = aoff(r, half * 4 + j);
                *(uint4*)(smem + AT_KH + o) = hh;
                *(uint4*)(smem + AT_KL + o) = ll;
                a = *(const float4*)(vg + j * 8);
                c = *(const float4*)(vg + j * 8 + 4);
                hh.x = packbf(a.x, a.y); hh.y = packbf(a.z, a.w);
                hh.z = packbf(c.x, c.y); hh.w = packbf(c.z, c.w);
                ll.x = packbf(lobf(a.x), lobf(a.y)); ll.y = packbf(lobf(a.z), lobf(a.w));
                ll.z = packbf(lobf(c.x), lobf(c.y)); ll.w = packbf(lobf(c.z), lobf(c.w));
                *(uint4*)(smem + AT_VH + o) = hh;
                *(uint4*)(smem + AT_VL + o) = ll;
            }
            if (maskp && tid < 64)
                ((float*)(smem + AT_MD))[tid] =
                    maskp[b * Lk + kt * 64 + tid] ? 0.f : -1e30f;
        }
        __syncthreads();

        // ---- S = Q K^T ----
        float s[8][4];
        #pragma unroll
        for (int i = 0; i < 8; i++) { s[i][0]=s[i][1]=s[i][2]=s[i][3]=0.f; }
        #pragma unroll
        for (int kc = 0; kc < 4; kc++) {
            #pragma unroll
            for (int np = 0; np < 4; np++) {
                uint32_t o = aoff(np * 16 + krow, kc * 2 + kcsel);
                uint32_t h0, h1, h2, h3, e0, e1, e2, e3;
                ldsm_x4(h0, h1, h2, h3, sb + AT_KH + o);
                ldsm_x4(e0, e1, e2, e3, sb + AT_KL + o);
                uint32_t bhA[2] = {h0, h1}, bhB[2] = {h2, h3};
                uint32_t blA[2] = {e0, e1}, blB[2] = {e2, e3};
                mma16816(s[np*2],   qh[kc], bhA);
                mma16816(s[np*2],   ql[kc], bhA);
                mma16816(s[np*2],   qh[kc], blA);
                mma16816(s[np*2+1], qh[kc], bhB);
                mma16816(s[np*2+1], ql[kc], bhB);
                mma16816(s[np*2+1], qh[kc], blB);
            }
        }
        // ---- mask ----
        if (maskp) {
            int cbase = 2 * (lane & 3);
            #pragma unroll
            for (int nt = 0; nt < 8; nt++) {
                float mA = madd[nt * 8 + cbase], mB = madd[nt * 8 + cbase + 1];
                s[nt][0] += mA; s[nt][1] += mB;
                s[nt][2] += mA; s[nt][3] += mB;
            }
        }
        // ---- online softmax ----
        float lm0 = -INFINITY, lm1 = -INFINITY;
        #pragma unroll
        for (int nt = 0; nt < 8; nt++) {
            lm0 = fmaxf(lm0, fmaxf(s[nt][0], s[nt][1]));
            lm1 = fmaxf(lm1, fmaxf(s[nt][2], s[nt][3]));
        }
        lm0 = fmaxf(lm0, __shfl_xor_sync(0xffffffffu, lm0, 1));
        lm0 = fmaxf(lm0, __shfl_xor_sync(0xffffffffu, lm0, 2));
        lm1 = fmaxf(lm1, __shfl_xor_sync(0xffffffffu, lm1, 1));
        lm1 = fmaxf(lm1, __shfl_xor_sync(0xffffffffu, lm1, 2));
        float mn0 = fmaxf(m0, lm0), mn1 = fmaxf(m1, lm1);
        float cr0 = __expf(m0 - mn0), cr1 = __expf(m1 - mn1);
        float sum0 = 0.f, sum1 = 0.f;
        #pragma unroll
        for (int nt = 0; nt < 8; nt++) {
            s[nt][0] = __expf(s[nt][0] - mn0); sum0 += s[nt][0];
            s[nt][1] = __expf(s[nt][1] - mn0); sum0 += s[nt][1];
            s[nt][2] = __expf(s[nt][2] - mn1); sum1 += s[nt][2];
            s[nt][3] = __expf(s[nt][3] - mn1); sum1 += s[nt][3];
        }
        sum0 += __shfl_xor_sync(0xffffffffu, sum0, 1);
        sum0 += __shfl_xor_sync(0xffffffffu, sum0, 2);
        sum1 += __shfl_xor_sync(0xffffffffu, sum1, 1);
        sum1 += __shfl_xor_sync(0xffffffffu, sum1, 2);
        l0 = l0 * cr0 + sum0; l1 = l1 * cr1 + sum1;
        m0 = mn0; m1 = mn1;
        // ---- rescale O ----
        #pragma unroll
        for (int nt = 0; nt < 8; nt++) {
            o_[nt][0] *= cr0; o_[nt][1] *= cr0;
            o_[nt][2] *= cr1; o_[nt][3] *= cr1;
        }
        // ---- O += P V ----
        #pragma unroll
        for (int kc = 0; kc < 4; kc++) {
            uint32_t pah[4], pal[4];
            float* sA = s[kc * 2];
            float* sB = s[kc * 2 + 1];
            pah[0] = packbf(sA[0], sA[1]); pah[1] = packbf(sA[2], sA[3]);
            pah[2] = packbf(sB[0], sB[1]); pah[3] = packbf(sB[2], sB[3]);
            pal[0] = packbf(lobf(sA[0]), lobf(sA[1]));
            pal[1] = packbf(lobf(sA[2]), lobf(sA[3]));
            pal[2] = packbf(lobf(sB[0]), lobf(sB[1]));
            pal[3] = packbf(lobf(sB[2]), lobf(sB[3]));
            #pragma unroll
            for (int dp = 0; dp < 4; dp++) {
                uint32_t o = aoff(kc * 16 + vrow, dp * 2 + vcsel);
                uint32_t v0, v1, v2, v3, u0, u1, u2, u3;
                ldsm_x4t(v0, v1, v2, v3, sb + AT_VH + o);
                ldsm_x4t(u0, u1, u2, u3, sb + AT_VL + o);
                uint32_t bhA[2] = {v0, v1}, bhB[2] = {v2, v3};
                uint32_t blA[2] = {u0, u1}, blB[2] = {u2, u3};
                mma16816(o_[dp*2],   pah, bhA);
                mma16816(o_[dp*2],   pal, bhA);
                mma16816(o_[dp*2],   pah, blA);
                mma16816(o_[dp*2+1], pah, bhB);
                mma16816(o_[dp*2+1], pal, bhB);
                mma16816(o_[dp*2+1], pah, blB);
            }
        }
    }

    // ---- write O ----
    float inv0 = 1.0f / l0, inv1 = 1.0f / l1;
    int r0 = w16 + (lane >> 2);
    int cg = h * Dd + 2 * (lane & 3);
    float* Ob = Op + (size_t)(b * Nn + n0) * Cc;
    #pragma unroll
    for (int nt = 0; nt < 8; nt++) {
        float2 p0, p1;
        p0.x = o_[nt][0] * inv0; p0.y = o_[nt][1] * inv0;
        p1.x = o_[nt][2] * inv1; p1.y = o_[nt][3] * inv1;
        *(float2*)(Ob + (size_t)r0 * Cc + cg + nt * 8) = p0;
        *(float2*)(Ob + (size_t)(r0 + 8) * Cc + cg + nt * 8) = p1;
    }
}

// ------------------------------- launch ------------------------------------
static void* sym_addr(const void* sym) {
    void* p = nullptr;
    cudaGetSymbolAddress(&p, sym);
    return p;
}

extern "C" void kernel_launch(void* const* d_in, const int* in_sizes, int n_in,
                              void* d_out, int out_size)
{
    const float* x        = (const float*)d_in[0];
    const float* c_dino   = (const float*)d_in[1];
    const float* c_text   = (const float*)d_in[2];
    const int*   mask     = (const int*)  d_in[3];
    const float* W_ada    = (const float*)d_in[4];
    const float* b_ada    = (const float*)d_in[5];
    const float* W_qkv    = (const float*)d_in[6];
    const float* b_qkv    = (const float*)d_in[7];
    const float* W_psa    = (const float*)d_in[8];
    const float* b_psa    = (const float*)d_in[9];
    const float* W_q      = (const float*)d_in[10];
    const float* b_q      = (const float*)d_in[11];
    const float* W_kv     = (const float*)d_in[12];
    const float* b_kv     = (const float*)d_in[13];
    const float* W_pca    = (const float*)d_in[14];
    const float* b_pca    = (const float*)d_in[15];
    const float* W_fc1    = (const float*)d_in[16];
    const float* b_fc1    = (const float*)d_in[17];
    const float* W_fc2    = (const float*)d_in[18];
    const float* b_fc2    = (const float*)d_in[19];
    float* out = (float*)d_out;

    float* ada  = (float*)sym_addr(g_ada);
    float* hbuf = (float*)sym_addr(g_h);
    float* qkv  = (float*)sym_addr(g_qkv);
    float* kv   = (float*)sym_addr(g_kv);
    float* attn = (float*)sym_addr(g_attn);
    float* x1   = (float*)sym_addr(g_x1);
    float* x2   = (float*)sym_addr(g_x2);
    float* mlp  = (float*)sym_addr(g_mlp);

    __nv_bfloat16* wqkv_h = (__nv_bfloat16*)sym_addr(g_wqkv_h);
    __nv_bfloat16* wqkv_l = (__nv_bfloat16*)sym_addr(g_wqkv_l);
    __nv_bfloat16* wpsa_h = (__nv_bfloat16*)sym_addr(g_wpsa_h);
    __nv_bfloat16* wpsa_l = (__nv_bfloat16*)sym_addr(g_wpsa_l);
    __nv_bfloat16* wq_h   = (__nv_bfloat16*)sym_addr(g_wq_h);
    __nv_bfloat16* wq_l   = (__nv_bfloat16*)sym_addr(g_wq_l);
    __nv_bfloat16* wkv_h  = (__nv_bfloat16*)sym_addr(g_wkv_h);
    __nv_bfloat16* wkv_l  = (__nv_bfloat16*)sym_addr(g_wkv_l);
    __nv_bfloat16* wpca_h = (__nv_bfloat16*)sym_addr(g_wpca_h);
    __nv_bfloat16* wpca_l = (__nv_bfloat16*)sym_addr(g_wpca_l);
    __nv_bfloat16* wfc1_h = (__nv_bfloat16*)sym_addr(g_wfc1_h);
    __nv_bfloat16* wfc1_l = (__nv_bfloat16*)sym_addr(g_wfc1_l);
    __nv_bfloat16* wfc2_h = (__nv_bfloat16*)sym_addr(g_wfc2_h);
    __nv_bfloat16* wfc2_l = (__nv_bfloat16*)sym_addr(g_wfc2_l);

    cudaFuncSetAttribute(attn_tc, cudaFuncAttributeMaxDynamicSharedMemorySize, AT_SMEM);
    cudaFuncSetAttribute(mm_gemm, cudaFuncAttributeMaxDynamicSharedMemorySize, MM_SMEM);

    // ---- weight prep (transpose + bf16 split) ----
    wprep_kernel<<<dim3(3*Cc/32, Cc/32), 256>>>(W_qkv, wqkv_h, wqkv_l, Cc, 3*Cc);
    wprep_kernel<<<dim3(Cc/32,   Cc/32), 256>>>(W_psa, wpsa_h, wpsa_l, Cc, Cc);
    wprep_kernel<<<dim3(Cc/32,   Cc/32), 256>>>(W_q,   wq_h,   wq_l,   Cc, Cc);
    wprep_kernel<<<dim3(2*Cc/32, Cc/32), 256>>>(W_kv,  wkv_h,  wkv_l,  Cc, 2*Cc);
    wprep_kernel<<<dim3(Cc/32,   Cc/32), 256>>>(W_pca, wpca_h, wpca_l, Cc, Cc);
    wprep_kernel<<<dim3(MLPD/32, Cc/32), 256>>>(W_fc1, wfc1_h, wfc1_l, Cc, MLPD);
    wprep_kernel<<<dim3(Cc/32, MLPD/32), 256>>>(W_fc2, wfc2_h, wfc2_l, MLPD, Cc);

    // ada
    ada_kernel<<<dim3(24, Bc), 256>>>(c_dino, W_ada, b_ada, ada);

    // ---- self attention ----
    lnmod_kernel<<<ROWS, 256>>>(x, ada, 0, hbuf);
    mm_gemm<<<dim3(3*Cc/128, ROWS/128), 256, MM_SMEM>>>(
        hbuf, wqkv_h, wqkv_l, b_qkv, nullptr, qkv, 3*Cc, Cc, 0);
    attn_tc<<<dim3(Nn/64, Hh, Bc), 128, AT_SMEM>>>(
        qkv, qkv + Cc, qkv + 2*Cc, attn, nullptr, 3*Cc, 3*Cc, Nn, 0.125f);
    mm_gemm<<<dim3(Cc/128, ROWS/128), 256, MM_SMEM>>>(
        attn, wpsa_h, wpsa_l, b_psa, x, x1, Cc, Cc, 0);

    // ---- cross attention ----
    lnmod_kernel<<<ROWS, 256>>>(x1, ada, 2*Cc, hbuf);
    mm_gemm<<<dim3(Cc/128, ROWS/128), 256, MM_SMEM>>>(
        hbuf, wq_h, wq_l, b_q, nullptr, qkv, Cc, Cc, 0);
    mm_gemm<<<dim3(2*Cc/128, (Bc*Mm)/128), 256, MM_SMEM>>>(
        c_text, wkv_h, wkv_l, b_kv, nullptr, kv, 2*Cc, Cc, 0);
    attn_tc<<<dim3(Nn/64, Hh, Bc), 128, AT_SMEM>>>(
        qkv, kv, kv + Cc, attn, mask, Cc, 2*Cc, Mm, 0.125f);
    mm_gemm<<<dim3(Cc/128, ROWS/128), 256, MM_SMEM>>>(
        attn, wpca_h, wpca_l, b_pca, x1, x2, Cc, Cc, 0);

    // ---- MLP ----
    lnmod_kernel<<<ROWS, 256>>>(x2, ada, 4*Cc, hbuf);
    mm_gemm<<<dim3(MLPD/128, ROWS/128), 256, MM_SMEM>>>(
        hbuf, wfc1_h, wfc1_l, b_fc1, nullptr, mlp, MLPD, Cc, 1);
    mm_gemm<<<dim3(Cc/128, ROWS/128), 256, MM_SMEM>>>(
        mlp, wfc2_h, wfc2_l, b_fc2, x2, out, Cc, MLPD, 0);
}

// round 6
// speedup vs baseline: 3.1168x; 1.3681x over previous
#include <cuda_runtime.h>
#include <cuda_bf16.h>
#include <math.h>
#include <stdint.h>

// ---------------------------------------------------------------------------
// DiT block. All GEMM/attention operands pre-split into bf16 hi/lo planes;
// mainloops are pure cp.async + ldmatrix + mma.sync (3-term split, fp32 acc).
// B=8, N=1024, M=128, C=1024, H=16, D=64, MLP=4096
// ---------------------------------------------------------------------------

#define Bc  8
#define Nn  1024
#define Mm  128
#define Cc  1024
#define Hh  16
#define Dd  64
#define MLPD 4096
#define ROWS (Bc * Nn)          // 8192

// ------------------------- scratch (device globals) ------------------------
__device__ float g_ada[Bc * 6 * Cc];
__device__ float g_x1[ROWS * Cc];
__device__ float g_x2[ROWS * Cc];

// activation planes (bf16 hi/lo)
__device__ __align__(16) __nv_bfloat16 g_hh[ROWS * Cc],   g_hl[ROWS * Cc];
__device__ __align__(16) __nv_bfloat16 g_qkvh[ROWS*3*Cc], g_qkvl[ROWS*3*Cc];
__device__ __align__(16) __nv_bfloat16 g_kvh[Bc*Mm*2*Cc], g_kvl[Bc*Mm*2*Cc];
__device__ __align__(16) __nv_bfloat16 g_cth[Bc*Mm*Cc],   g_ctl[Bc*Mm*Cc];
__device__ __align__(16) __nv_bfloat16 g_ath[ROWS * Cc],  g_atl[ROWS * Cc];
__device__ __align__(16) __nv_bfloat16 g_mlph[ROWS*MLPD], g_mlpl[ROWS*MLPD];

// transposed + bf16-split weights: [N][K] hi/lo planes
__device__ __align__(16) __nv_bfloat16 g_wqkv_h[Cc * 3 * Cc], g_wqkv_l[Cc * 3 * Cc];
__device__ __align__(16) __nv_bfloat16 g_wpsa_h[Cc * Cc],     g_wpsa_l[Cc * Cc];
__device__ __align__(16) __nv_bfloat16 g_wq_h[Cc * Cc],       g_wq_l[Cc * Cc];
__device__ __align__(16) __nv_bfloat16 g_wkv_h[Cc * 2 * Cc],  g_wkv_l[Cc * 2 * Cc];
__device__ __align__(16) __nv_bfloat16 g_wpca_h[Cc * Cc],     g_wpca_l[Cc * Cc];
__device__ __align__(16) __nv_bfloat16 g_wfc1_h[Cc * MLPD],   g_wfc1_l[Cc * MLPD];
__device__ __align__(16) __nv_bfloat16 g_wfc2_h[MLPD * Cc],   g_wfc2_l[MLPD * Cc];

// ------------------------------ ptx helpers --------------------------------
__device__ __forceinline__ uint32_t smem_u32(const void* p) {
    uint32_t a;
    asm("{ .reg .u64 t; cvta.to.shared.u64 t, %1; cvt.u32.u64 %0, t; }" : "=r"(a) : "l"(p));
    return a;
}
__device__ __forceinline__ void ldsm_x4(uint32_t& r0, uint32_t& r1, uint32_t& r2,
                                        uint32_t& r3, uint32_t a) {
    asm volatile("ldmatrix.sync.aligned.m8n8.x4.shared.b16 {%0,%1,%2,%3}, [%4];"
                 : "=r"(r0), "=r"(r1), "=r"(r2), "=r"(r3) : "r"(a));
}
__device__ __forceinline__ void ldsm_x4t(uint32_t& r0, uint32_t& r1, uint32_t& r2,
                                         uint32_t& r3, uint32_t a) {
    asm volatile("ldmatrix.sync.aligned.m8n8.x4.trans.shared.b16 {%0,%1,%2,%3}, [%4];"
                 : "=r"(r0), "=r"(r1), "=r"(r2), "=r"(r3) : "r"(a));
}
__device__ __forceinline__ void mma16816(float* d, const uint32_t* a, const uint32_t* b) {
    asm volatile(
        "mma.sync.aligned.m16n8k16.row.col.f32.bf16.bf16.f32 "
        "{%0,%1,%2,%3}, {%4,%5,%6,%7}, {%8,%9}, {%0,%1,%2,%3};"
        : "+f"(d[0]), "+f"(d[1]), "+f"(d[2]), "+f"(d[3])
        : "r"(a[0]), "r"(a[1]), "r"(a[2]), "r"(a[3]), "r"(b[0]), "r"(b[1]));
}
__device__ __forceinline__ void cp16(uint32_t dst, const void* src) {
    asm volatile("cp.async.cg.shared.global [%0], [%1], 16;" :: "r"(dst), "l"(src));
}
#define CP_COMMIT asm volatile("cp.async.commit_group;" ::: "memory")
#define CP_WAIT0  asm volatile("cp.async.wait_group 0;" ::: "memory")
#define CP_WAIT1  asm volatile("cp.async.wait_group 1;" ::: "memory")

// GEMM tile swizzle: 64B rows (4 chunks of 16B)
__device__ __forceinline__ uint32_t toff(int r, int c) {
    return ((uint32_t)r << 6) + ((uint32_t)((c ^ (r >> 1)) & 3) << 4);
}
// attention tile swizzle: 128B rows (8 chunks of 16B)
__device__ __forceinline__ uint32_t aoff(int r, int c) {
    return ((uint32_t)r << 7) + ((uint32_t)((c ^ (r & 7)) & 7) << 4);
}

// ------------------------------ misc helpers -------------------------------
__device__ __forceinline__ float gelu_tanh(float x) {
    float x3 = x * x * x;
    return 0.5f * x * (1.0f + tanhf(0.7978845608028654f * (x + 0.044715f * x3)));
}
__device__ __forceinline__ float block_sum_1024(float v) {
    __shared__ float red[8];
    __shared__ float bcast;
    int lane = threadIdx.x & 31, wid = threadIdx.x >> 5;
    #pragma unroll
    for (int o = 16; o; o >>= 1) v += __shfl_xor_sync(0xffffffffu, v, o);
    __syncthreads();
    if (lane == 0) red[wid] = v;
    __syncthreads();
    if (threadIdx.x == 0) {
        float t = 0.f;
        #pragma unroll
        for (int i = 0; i < 8; i++) t += red[i];
        bcast = t;
    }
    __syncthreads();
    return bcast;
}
__device__ __forceinline__ uint32_t packbf(float x, float y) {
    __nv_bfloat16 a = __float2bfloat16(x), b = __float2bfloat16(y);
    return ((uint32_t)__bfloat16_as_ushort(b) << 16) | __bfloat16_as_ushort(a);
}
__device__ __forceinline__ float lobf(float x) {
    return x - __bfloat162float(__float2bfloat16(x));
}

// -------------------- weight prep: W[K][N] -> Wt_hi/lo [N][K] ---------------
__global__ __launch_bounds__(256) void wprep_kernel(
    const float* __restrict__ W, __nv_bfloat16* __restrict__ Th,
    __nv_bfloat16* __restrict__ Tl, int K, int N)
{
    __shared__ float t[32][33];
    int n0 = blockIdx.x * 32, k0 = blockIdx.y * 32;
    int tx = threadIdx.x & 31, ty = threadIdx.x >> 5;
    #pragma unroll
    for (int i = 0; i < 32; i += 8)
        t[ty + i][tx] = W[(size_t)(k0 + ty + i) * N + n0 + tx];
    __syncthreads();
    #pragma unroll
    for (int i = 0; i < 32; i += 8) {
        float v = t[tx][ty + i];
        __nv_bfloat16 h = __float2bfloat16(v);
        __nv_bfloat16 l = __float2bfloat16(v - __bfloat162float(h));
        size_t o = (size_t)(n0 + ty + i) * K + k0 + tx;
        Th[o] = h; Tl[o] = l;
    }
}

// ------------------ c_text -> bf16 hi/lo planes ----------------------------
__global__ __launch_bounds__(256) void ct_split_kernel(
    const float* __restrict__ X, __nv_bfloat16* __restrict__ Ph,
    __nv_bfloat16* __restrict__ Pl)
{
    size_t i = ((size_t)blockIdx.x * 256 + threadIdx.x) * 4;
    float4 v = *(const float4*)(X + i);
    uint2 vh, vl;
    vh.x = packbf(v.x, v.y); vh.y = packbf(v.z, v.w);
    vl.x = packbf(lobf(v.x), lobf(v.y)); vl.y = packbf(lobf(v.z), lobf(v.w));
    *(uint2*)(Ph + i) = vh;
    *(uint2*)(Pl + i) = vl;
}

// ----------------------- ada = silu(c_dino) @ W_ada + b --------------------
__global__ __launch_bounds__(256) void ada_kernel(
    const float* __restrict__ cdino, const float* __restrict__ W,
    const float* __restrict__ bvec, float* __restrict__ out)
{
    __shared__ float s[Cc];
    int b = blockIdx.y, tid = threadIdx.x;
    for (int i = tid; i < Cc; i += 256) {
        float v = cdino[b * Cc + i];
        s[i] = v / (1.0f + __expf(-v));
    }
    __syncthreads();
    int n = blockIdx.x * 256 + tid;
    float acc = 0.f;
    #pragma unroll 4
    for (int k = 0; k < Cc; k++)
        acc = fmaf(s[k], W[(size_t)k * (6 * Cc) + n], acc);
    out[b * 6 * Cc + n] = acc + bvec[n];
}

// ---------- h = modulate(ln(x), shift, scale) -> bf16 hi/lo planes ---------
__global__ __launch_bounds__(256) void lnmod_kernel(
    const float* __restrict__ X, const float* __restrict__ ada,
    int shiftOff, __nv_bfloat16* __restrict__ Yh, __nv_bfloat16* __restrict__ Yl)
{
    int row = blockIdx.x;
    int b = row >> 10;
    const float* xr = X + (size_t)row * Cc;
    int c = threadIdx.x * 4;

    float4 v = *(const float4*)(xr + c);
    float mu = block_sum_1024(v.x + v.y + v.z + v.w) * (1.0f / Cc);
    float c0 = v.x - mu, c1 = v.y - mu, c2 = v.z - mu, c3 = v.w - mu;
    float var = block_sum_1024(c0*c0 + c1*c1 + c2*c2 + c3*c3) * (1.0f / Cc);
    float rstd = rsqrtf(var + 1e-6f);

    const float* sh = ada + b * 6 * Cc + shiftOff;
    const float* sc = sh + Cc;
    float4 shv = *(const float4*)(sh + c);
    float4 scv = *(const float4*)(sc + c);
    float4 o;
    o.x = c0 * rstd * (1.0f + scv.x) + shv.x;
    o.y = c1 * rstd * (1.0f + scv.y) + shv.y;
    o.z = c2 * rstd * (1.0f + scv.z) + shv.z;
    o.w = c3 * rstd * (1.0f + scv.w) + shv.w;
    uint2 vh, vl;
    vh.x = packbf(o.x, o.y); vh.y = packbf(o.z, o.w);
    vl.x = packbf(lobf(o.x), lobf(o.y)); vl.y = packbf(lobf(o.z), lobf(o.w));
    *(uint2*)(Yh + (size_t)row * Cc + c) = vh;
    *(uint2*)(Yl + (size_t)row * Cc + c) = vl;
}

// --------------------------- mma.sync GEMM ---------------------------------
// A, B both pre-split bf16 planes [M][K]/[N][K]. Tile 128x128x32, 8 warps,
// 3-stage cp.async pipeline.
// mode 0: Cf = D + bias (+res)        (fp32 out)
// mode 1: gelu(D + bias) -> Ch/Cl planes
// mode 2: D + bias -> Ch/Cl planes
#define PL_AH 0
#define PL_AL 8192
#define PL_BH 16384
#define PL_BL 24576
#define MSTAGE 32768
#define MM_SMEM (3 * MSTAGE)
#define MBK 32

__global__ __launch_bounds__(256) void mm_gemm(
    const __nv_bfloat16* __restrict__ Ahp, const __nv_bfloat16* __restrict__ Alp,
    const __nv_bfloat16* __restrict__ Bhp, const __nv_bfloat16* __restrict__ Blp,
    const float* __restrict__ bias, const float* __restrict__ res,
    float* __restrict__ Cf, __nv_bfloat16* __restrict__ Ch,
    __nv_bfloat16* __restrict__ Cl, int N, int K, int mode)
{
    extern __shared__ char smem[];
    uint32_t sb = smem_u32(smem);
    const int tid = threadIdx.x, lane = tid & 31, warp = tid >> 5;
    const int wm = warp >> 2, wn = warp & 3;
    const int row0 = blockIdx.y * 128, col0 = blockIdx.x * 128;

    const int lr_ = tid >> 1;
    const int cb_ = (tid & 1) * 2;
    const __nv_bfloat16* Agh = Ahp + (size_t)(row0 + lr_) * K + cb_ * 8;
    const __nv_bfloat16* Agl = Alp + (size_t)(row0 + lr_) * K + cb_ * 8;
    const __nv_bfloat16* Bgh = Bhp + (size_t)(col0 + lr_) * K + cb_ * 8;
    const __nv_bfloat16* Bgl = Blp + (size_t)(col0 + lr_) * K + cb_ * 8;
    const uint32_t sA0 = toff(lr_, cb_), sA1 = toff(lr_, cb_ + 1);

    float d[4][4][4];
    #pragma unroll
    for (int i = 0; i < 4; i++)
        #pragma unroll
        for (int j = 0; j < 4; j++)
            d[i][j][0] = d[i][j][1] = d[i][j][2] = d[i][j][3] = 0.f;

    const int nk = K / MBK;

    #define MM_ISSUE(kt, stg) do {                                   \
        uint32_t bse = sb + (stg) * MSTAGE;                          \
        const __nv_bfloat16* p_;                                     \
        p_ = Agh + (kt) * MBK;                                       \
        cp16(bse + PL_AH + sA0, p_); cp16(bse + PL_AH + sA1, p_ + 8);\
        p_ = Agl + (kt) * MBK;                                       \
        cp16(bse + PL_AL + sA0, p_); cp16(bse + PL_AL + sA1, p_ + 8);\
        p_ = Bgh + (kt) * MBK;                                       \
        cp16(bse + PL_BH + sA0, p_); cp16(bse + PL_BH + sA1, p_ + 8);\
        p_ = Bgl + (kt) * MBK;                                       \
        cp16(bse + PL_BL + sA0, p_); cp16(bse + PL_BL + sA1, p_ + 8);\
        CP_COMMIT;                                                   \
    } while (0)

    MM_ISSUE(0, 0);
    if (nk > 1) MM_ISSUE(1, 1);

    const int g = lane >> 3, lq = lane & 7;

    for (int kt = 0; kt < nk; kt++) {
        if (kt + 1 < nk) { CP_WAIT1; } else { CP_WAIT0; }
        __syncthreads();
        if (kt + 2 < nk) {
            int stg2 = (kt + 2) % 3;
            MM_ISSUE(kt + 2, stg2);
        }
        const uint32_t base = sb + (kt % 3) * MSTAGE;

        #pragma unroll
        for (int ks = 0; ks < 2; ks++) {
            uint32_t ah[4][4], al[4][4], bh[4][2], bl[4][2];
            const int arow = ((g & 1) << 3) + lq;
            const int acol = 2 * ks + (g >> 1);
            #pragma unroll
            for (int mi = 0; mi < 4; mi++) {
                uint32_t o = toff(wm * 64 + mi * 16 + arow, acol);
                ldsm_x4(ah[mi][0], ah[mi][1], ah[mi][2], ah[mi][3], base + PL_AH + o);
                ldsm_x4(al[mi][0], al[mi][1], al[mi][2], al[mi][3], base + PL_AL + o);
            }
            const int brow = ((g >> 1) << 3) + lq;
            const int bcol = 2 * ks + (g & 1);
            #pragma unroll
            for (int nh = 0; nh < 2; nh++) {
                uint32_t o = toff(wn * 32 + nh * 16 + brow, bcol);
                uint32_t t0, t1, t2, t3;
                ldsm_x4(t0, t1, t2, t3, base + PL_BH + o);
                bh[nh*2][0] = t0; bh[nh*2][1] = t1;
                bh[nh*2+1][0] = t2; bh[nh*2+1][1] = t3;
                ldsm_x4(t0, t1, t2, t3, base + PL_BL + o);
                bl[nh*2][0] = t0; bl[nh*2][1] = t1;
                bl[nh*2+1][0] = t2; bl[nh*2+1][1] = t3;
            }
            #pragma unroll
            for (int mi = 0; mi < 4; mi++)
                #pragma unroll
                for (int ni = 0; ni < 4; ni++) {
                    mma16816(d[mi][ni], ah[mi], bh[ni]);
                    mma16816(d[mi][ni], al[mi], bh[ni]);
                    mma16816(d[mi][ni], ah[mi], bl[ni]);
                }
        }
    }

    // ---- epilogue ----
    const int rr = lane >> 2, cc2 = (lane & 3) * 2;
    #pragma unroll
    for (int mi = 0; mi < 4; mi++) {
        #pragma unroll
        for (int ni = 0; ni < 4; ni++) {
            int r0g = row0 + wm * 64 + mi * 16 + rr;
            int cg  = col0 + wn * 32 + ni * 8 + cc2;
            float b0 = bias[cg], b1 = bias[cg + 1];
            #pragma unroll
            for (int hrow = 0; hrow < 2; hrow++) {
                int r = r0g + hrow * 8;
                float v0 = d[mi][ni][hrow * 2 + 0] + b0;
                float v1 = d[mi][ni][hrow * 2 + 1] + b1;
                if (mode == 0) {
                    if (res) {
                        float2 rv = *(const float2*)(res + (size_t)r * N + cg);
                        v0 += rv.x; v1 += rv.y;
                    }
                    float2 o; o.x = v0; o.y = v1;
                    *(float2*)(Cf + (size_t)r * N + cg) = o;
                } else {
                    if (mode == 1) { v0 = gelu_tanh(v0); v1 = gelu_tanh(v1); }
                    *(uint32_t*)(Ch + (size_t)r * N + cg) = packbf(v0, v1);
                    *(uint32_t*)(Cl + (size_t)r * N + cg) = packbf(lobf(v0), lobf(v1));
                }
            }
        }
    }
}

// ------------------- tensor-core flash attention ---------------------------
// 4 warps, 64 q x 64 k tiles, D=64. All inputs pre-split bf16 planes.
// Output written as bf16 hi/lo planes for the following proj GEMM.
#define AT_QH 0
#define AT_QL 8192
#define AT_KH 16384
#define AT_KL 24576
#define AT_VH 32768
#define AT_VL 40960
#define AT_MD 49152
#define AT_SMEM 49408

__global__ __launch_bounds__(128) void attn_tc(
    const __nv_bfloat16* __restrict__ Qh, const __nv_bfloat16* __restrict__ Ql,
    const __nv_bfloat16* __restrict__ Kh, const __nv_bfloat16* __restrict__ Kl,
    const __nv_bfloat16* __restrict__ Vh, const __nv_bfloat16* __restrict__ Vl,
    __nv_bfloat16* __restrict__ Oh, __nv_bfloat16* __restrict__ Ol,
    const int* __restrict__ maskp,
    int qStride, int kvStride, int Lk, float scale)
{
    extern __shared__ char smem[];
    uint32_t sb = smem_u32(smem);
    const int tid = threadIdx.x, lane = tid & 31, warp = tid >> 5;
    const int b = blockIdx.z, h = blockIdx.y, n0 = blockIdx.x * 64;
    const int w16 = warp * 16;

    // ---- load Q planes via cp.async ----
    #pragma unroll
    for (int it = 0; it < 4; it++) {
        int cid = tid + it * 128;
        int r = cid >> 3, c = cid & 7;
        size_t gq = (size_t)(b * Nn + n0 + r) * qStride + h * Dd + c * 8;
        uint32_t o = aoff(r, c);
        cp16(sb + AT_QH + o, Qh + gq);
        cp16(sb + AT_QL + o, Ql + gq);
    }
    CP_COMMIT; CP_WAIT0;
    __syncthreads();

    // ---- Q A-fragments (registers for whole kernel) ----
    uint32_t qh[4][4], ql[4][4];
    {
        int rr = (lane & 7) + 8 * ((lane >> 3) & 1);
        int cc = lane >> 4;
        #pragma unroll
        for (int kc = 0; kc < 4; kc++) {
            uint32_t o = aoff(w16 + rr, kc * 2 + cc);
            ldsm_x4(qh[kc][0], qh[kc][1], qh[kc][2], qh[kc][3], sb + AT_QH + o);
            ldsm_x4(ql[kc][0], ql[kc][1], ql[kc][2], ql[kc][3], sb + AT_QL + o);
        }
    }

    float o_[8][4];
    #pragma unroll
    for (int i = 0; i < 8; i++) { o_[i][0]=o_[i][1]=o_[i][2]=o_[i][3]=0.f; }
    float m0 = -INFINITY, m1 = -INFINITY, l0 = 0.f, l1 = 0.f;

    const int krow = (lane & 7) + 8 * (lane >> 4);
    const int kcsel = (lane >> 3) & 1;
    const int vrow = lane & 15, vcsel = lane >> 4;
    const float* madd = (const float*)(smem + AT_MD);

    const int nTiles = Lk >> 6;
    for (int kt = 0; kt < nTiles; kt++) {
        __syncthreads();   // prior tile's K/V reads done
        #pragma unroll
        for (int it = 0; it < 4; it++) {
            int cid = tid + it * 128;
            int r = cid >> 3, c = cid & 7;
            size_t gk = (size_t)(b * Lk + kt * 64 + r) * kvStride + h * Dd + c * 8;
            uint32_t o = aoff(r, c);
            cp16(sb + AT_KH + o, Kh + gk);
            cp16(sb + AT_KL + o, Kl + gk);
            cp16(sb + AT_VH + o, Vh + gk);
            cp16(sb + AT_VL + o, Vl + gk);
        }
        if (maskp && tid < 64)
            ((float*)(smem + AT_MD))[tid] =
                maskp[b * Lk + kt * 64 + tid] ? 0.f : -1e30f;
        CP_COMMIT; CP_WAIT0;
        __syncthreads();

        // ---- S = Q K^T ----
        float s[8][4];
        #pragma unroll
        for (int i = 0; i < 8; i++) { s[i][0]=s[i][1]=s[i][2]=s[i][3]=0.f; }
        #pragma unroll
        for (int kc = 0; kc < 4; kc++) {
            #pragma unroll
            for (int np = 0; np < 4; np++) {
                uint32_t o = aoff(np * 16 + krow, kc * 2 + kcsel);
                uint32_t h0, h1, h2, h3, e0, e1, e2, e3;
                ldsm_x4(h0, h1, h2, h3, sb + AT_KH + o);
                ldsm_x4(e0, e1, e2, e3, sb + AT_KL + o);
                uint32_t bhA[2] = {h0, h1}, bhB[2] = {h2, h3};
                uint32_t blA[2] = {e0, e1}, blB[2] = {e2, e3};
                mma16816(s[np*2],   qh[kc], bhA);
                mma16816(s[np*2],   ql[kc], bhA);
                mma16816(s[np*2],   qh[kc], blA);
                mma16816(s[np*2+1], qh[kc], bhB);
                mma16816(s[np*2+1], ql[kc], bhB);
                mma16816(s[np*2+1], qh[kc], blB);
            }
        }
        // scale (Q not pre-scaled)
        #pragma unroll
        for (int nt = 0; nt < 8; nt++) {
            s[nt][0] *= scale; s[nt][1] *= scale;
            s[nt][2] *= scale; s[nt][3] *= scale;
        }
        if (maskp) {
            int cbase = 2 * (lane & 3);
            #pragma unroll
            for (int nt = 0; nt < 8; nt++) {
                float mA = madd[nt * 8 + cbase], mB = madd[nt * 8 + cbase + 1];
                s[nt][0] += mA; s[nt][1] += mB;
                s[nt][2] += mA; s[nt][3] += mB;
            }
        }
        // ---- online softmax ----
        float lm0 = -INFINITY, lm1 = -INFINITY;
        #pragma unroll
        for (int nt = 0; nt < 8; nt++) {
            lm0 = fmaxf(lm0, fmaxf(s[nt][0], s[nt][1]));
            lm1 = fmaxf(lm1, fmaxf(s[nt][2], s[nt][3]));
        }
        lm0 = fmaxf(lm0, __shfl_xor_sync(0xffffffffu, lm0, 1));
        lm0 = fmaxf(lm0, __shfl_xor_sync(0xffffffffu, lm0, 2));
        lm1 = fmaxf(lm1, __shfl_xor_sync(0xffffffffu, lm1, 1));
        lm1 = fmaxf(lm1, __shfl_xor_sync(0xffffffffu, lm1, 2));
        float mn0 = fmaxf(m0, lm0), mn1 = fmaxf(m1, lm1);
        float cr0 = __expf(m0 - mn0), cr1 = __expf(m1 - mn1);
        float sum0 = 0.f, sum1 = 0.f;
        #pragma unroll
        for (int nt = 0; nt < 8; nt++) {
            s[nt][0] = __expf(s[nt][0] - mn0); sum0 += s[nt][0];
            s[nt][1] = __expf(s[nt][1] - mn0); sum0 += s[nt][1];
            s[nt][2] = __expf(s[nt][2] - mn1); sum1 += s[nt][2];
            s[nt][3] = __expf(s[nt][3] - mn1); sum1 += s[nt][3];
        }
        sum0 += __shfl_xor_sync(0xffffffffu, sum0, 1);
        sum0 += __shfl_xor_sync(0xffffffffu, sum0, 2);
        sum1 += __shfl_xor_sync(0xffffffffu, sum1, 1);
        sum1 += __shfl_xor_sync(0xffffffffu, sum1, 2);
        l0 = l0 * cr0 + sum0; l1 = l1 * cr1 + sum1;
        m0 = mn0; m1 = mn1;
        #pragma unroll
        for (int nt = 0; nt < 8; nt++) {
            o_[nt][0] *= cr0; o_[nt][1] *= cr0;
            o_[nt][2] *= cr1; o_[nt][3] *= cr1;
        }
        // ---- O += P V ----
        #pragma unroll
        for (int kc = 0; kc < 4; kc++) {
            uint32_t pah[4], pal[4];
            float* sA = s[kc * 2];
            float* sB = s[kc * 2 + 1];
            pah[0] = packbf(sA[0], sA[1]); pah[1] = packbf(sA[2], sA[3]);
            pah[2] = packbf(sB[0], sB[1]); pah[3] = packbf(sB[2], sB[3]);
            pal[0] = packbf(lobf(sA[0]), lobf(sA[1]));
            pal[1] = packbf(lobf(sA[2]), lobf(sA[3]));
            pal[2] = packbf(lobf(sB[0]), lobf(sB[1]));
            pal[3] = packbf(lobf(sB[2]), lobf(sB[3]));
            #pragma unroll
            for (int dp = 0; dp < 4; dp++) {
                uint32_t o = aoff(kc * 16 + vrow, dp * 2 + vcsel);
                uint32_t v0, v1, v2, v3, u0, u1, u2, u3;
                ldsm_x4t(v0, v1, v2, v3, sb + AT_VH + o);
                ldsm_x4t(u0, u1, u2, u3, sb + AT_VL + o);
                uint32_t bhA[2] = {v0, v1}, bhB[2] = {v2, v3};
                uint32_t blA[2] = {u0, u1}, blB[2] = {u2, u3};
                mma16816(o_[dp*2],   pah, bhA);
                mma16816(o_[dp*2],   pal, bhA);
                mma16816(o_[dp*2],   pah, blA);
                mma16816(o_[dp*2+1], pah, bhB);
                mma16816(o_[dp*2+1], pal, bhB);
                mma16816(o_[dp*2+1], pah, blB);
            }
        }
    }

    // ---- write O planes ----
    float inv0 = 1.0f / l0, inv1 = 1.0f / l1;
    int r0 = w16 + (lane >> 2);
    int cg = h * Dd + 2 * (lane & 3);
    size_t rb = (size_t)(b * Nn + n0);
    #pragma unroll
    for (int nt = 0; nt < 8; nt++) {
        float v0 = o_[nt][0] * inv0, v1 = o_[nt][1] * inv0;
        float w0 = o_[nt][2] * inv1, w1 = o_[nt][3] * inv1;
        size_t o0 = (rb + r0) * Cc + cg + nt * 8;
        size_t o1 = (rb + r0 + 8) * Cc + cg + nt * 8;
        *(uint32_t*)(Oh + o0) = packbf(v0, v1);
        *(uint32_t*)(Ol + o0) = packbf(lobf(v0), lobf(v1));
        *(uint32_t*)(Oh + o1) = packbf(w0, w1);
        *(uint32_t*)(Ol + o1) = packbf(lobf(w0), lobf(w1));
    }
}

// ------------------------------- launch ------------------------------------
static void* sym_addr(const void* sym) {
    void* p = nullptr;
    cudaGetSymbolAddress(&p, sym);
    return p;
}

extern "C" void kernel_launch(void* const* d_in, const int* in_sizes, int n_in,
                              void* d_out, int out_size)
{
    const float* x        = (const float*)d_in[0];
    const float* c_dino   = (const float*)d_in[1];
    const float* c_text   = (const float*)d_in[2];
    const int*   mask     = (const int*)  d_in[3];
    const float* W_ada    = (const float*)d_in[4];
    const float* b_ada    = (const float*)d_in[5];
    const float* W_qkv    = (const float*)d_in[6];
    const float* b_qkv    = (const float*)d_in[7];
    const float* W_psa    = (const float*)d_in[8];
    const float* b_psa    = (const float*)d_in[9];
    const float* W_q      = (const float*)d_in[10];
    const float* b_q      = (const float*)d_in[11];
    const float* W_kv     = (const float*)d_in[12];
    const float* b_kv     = (const float*)d_in[13];
    const float* W_pca    = (const float*)d_in[14];
    const float* b_pca    = (const float*)d_in[15];
    const float* W_fc1    = (const float*)d_in[16];
    const float* b_fc1    = (const float*)d_in[17];
    const float* W_fc2    = (const float*)d_in[18];
    const float* b_fc2    = (const float*)d_in[19];
    float* out = (float*)d_out;

    float* ada  = (float*)sym_addr(g_ada);
    float* x1   = (float*)sym_addr(g_x1);
    float* x2   = (float*)sym_addr(g_x2);

    __nv_bfloat16* hh   = (__nv_bfloat16*)sym_addr(g_hh);
    __nv_bfloat16* hl   = (__nv_bfloat16*)sym_addr(g_hl);
    __nv_bfloat16* qkvh = (__nv_bfloat16*)sym_addr(g_qkvh);
    __nv_bfloat16* qkvl = (__nv_bfloat16*)sym_addr(g_qkvl);
    __nv_bfloat16* kvh  = (__nv_bfloat16*)sym_addr(g_kvh);
    __nv_bfloat16* kvl  = (__nv_bfloat16*)sym_addr(g_kvl);
    __nv_bfloat16* cth  = (__nv_bfloat16*)sym_addr(g_cth);
    __nv_bfloat16* ctl  = (__nv_bfloat16*)sym_addr(g_ctl);
    __nv_bfloat16* ath  = (__nv_bfloat16*)sym_addr(g_ath);
    __nv_bfloat16* atl  = (__nv_bfloat16*)sym_addr(g_atl);
    __nv_bfloat16* mlph = (__nv_bfloat16*)sym_addr(g_mlph);
    __nv_bfloat16* mlpl = (__nv_bfloat16*)sym_addr(g_mlpl);

    __nv_bfloat16* wqkv_h = (__nv_bfloat16*)sym_addr(g_wqkv_h);
    __nv_bfloat16* wqkv_l = (__nv_bfloat16*)sym_addr(g_wqkv_l);
    __nv_bfloat16* wpsa_h = (__nv_bfloat16*)sym_addr(g_wpsa_h);
    __nv_bfloat16* wpsa_l = (__nv_bfloat16*)sym_addr(g_wpsa_l);
    __nv_bfloat16* wq_h   = (__nv_bfloat16*)sym_addr(g_wq_h);
    __nv_bfloat16* wq_l   = (__nv_bfloat16*)sym_addr(g_wq_l);
    __nv_bfloat16* wkv_h  = (__nv_bfloat16*)sym_addr(g_wkv_h);
    __nv_bfloat16* wkv_l  = (__nv_bfloat16*)sym_addr(g_wkv_l);
    __nv_bfloat16* wpca_h = (__nv_bfloat16*)sym_addr(g_wpca_h);
    __nv_bfloat16* wpca_l = (__nv_bfloat16*)sym_addr(g_wpca_l);
    __nv_bfloat16* wfc1_h = (__nv_bfloat16*)sym_addr(g_wfc1_h);
    __nv_bfloat16* wfc1_l = (__nv_bfloat16*)sym_addr(g_wfc1_l);
    __nv_bfloat16* wfc2_h = (__nv_bfloat16*)sym_addr(g_wfc2_h);
    __nv_bfloat16* wfc2_l = (__nv_bfloat16*)sym_addr(g_wfc2_l);

    cudaFuncSetAttribute(attn_tc, cudaFuncAttributeMaxDynamicSharedMemorySize, AT_SMEM);
    cudaFuncSetAttribute(mm_gemm, cudaFuncAttributeMaxDynamicSharedMemorySize, MM_SMEM);

    // ---- weight prep ----
    wprep_kernel<<<dim3(3*Cc/32, Cc/32), 256>>>(W_qkv, wqkv_h, wqkv_l, Cc, 3*Cc);
    wprep_kernel<<<dim3(Cc/32,   Cc/32), 256>>>(W_psa, wpsa_h, wpsa_l, Cc, Cc);
    wprep_kernel<<<dim3(Cc/32,   Cc/32), 256>>>(W_q,   wq_h,   wq_l,   Cc, Cc);
    wprep_kernel<<<dim3(2*Cc/32, Cc/32), 256>>>(W_kv,  wkv_h,  wkv_l,  Cc, 2*Cc);
    wprep_kernel<<<dim3(Cc/32,   Cc/32), 256>>>(W_pca, wpca_h, wpca_l, Cc, Cc);
    wprep_kernel<<<dim3(MLPD/32, Cc/32), 256>>>(W_fc1, wfc1_h, wfc1_l, Cc, MLPD);
    wprep_kernel<<<dim3(Cc/32, MLPD/32), 256>>>(W_fc2, wfc2_h, wfc2_l, MLPD, Cc);

    ada_kernel<<<dim3(24, Bc), 256>>>(c_dino, W_ada, b_ada, ada);
    ct_split_kernel<<<(Bc*Mm*Cc)/1024, 256>>>(c_text, cth, ctl);

    // ---- self attention ----
    lnmod_kernel<<<ROWS, 256>>>(x, ada, 0, hh, hl);
    mm_gemm<<<dim3(3*Cc/128, ROWS/128), 256, MM_SMEM>>>(
        hh, hl, wqkv_h, wqkv_l, b_qkv, nullptr, nullptr, qkvh, qkvl, 3*Cc, Cc, 2);
    attn_tc<<<dim3(Nn/64, Hh, Bc), 128, AT_SMEM>>>(
        qkvh, qkvl, qkvh + Cc, qkvl + Cc, qkvh + 2*Cc, qkvl + 2*Cc,
        ath, atl, nullptr, 3*Cc, 3*Cc, Nn, 0.125f);
    mm_gemm<<<dim3(Cc/128, ROWS/128), 256, MM_SMEM>>>(
        ath, atl, wpsa_h, wpsa_l, b_psa, x, x1, nullptr, nullptr, Cc, Cc, 0);

    // ---- cross attention ----
    lnmod_kernel<<<ROWS, 256>>>(x1, ada, 2*Cc, hh, hl);
    mm_gemm<<<dim3(Cc/128, ROWS/128), 256, MM_SMEM>>>(
        hh, hl, wq_h, wq_l, b_q, nullptr, nullptr, qkvh, qkvl, Cc, Cc, 2);
    mm_gemm<<<dim3(2*Cc/128, (Bc*Mm)/128), 256, MM_SMEM>>>(
        cth, ctl, wkv_h, wkv_l, b_kv, nullptr, nullptr, kvh, kvl, 2*Cc, Cc, 2);
    attn_tc<<<dim3(Nn/64, Hh, Bc), 128, AT_SMEM>>>(
        qkvh, qkvl, kvh, kvl, kvh + Cc, kvl + Cc,
        ath, atl, mask, Cc, 2*Cc, Mm, 0.125f);
    mm_gemm<<<dim3(Cc/128, ROWS/128), 256, MM_SMEM>>>(
        ath, atl, wpca_h, wpca_l, b_pca, x1, x2, nullptr, nullptr, Cc, Cc, 0);

    // ---- MLP ----
    lnmod_kernel<<<ROWS, 256>>>(x2, ada, 4*Cc, hh, hl);
    mm_gemm<<<dim3(MLPD/128, ROWS/128), 256, MM_SMEM>>>(
        hh, hl, wfc1_h, wfc1_l, b_fc1, nullptr, nullptr, mlph, mlpl, MLPD, Cc, 1);
    mm_gemm<<<dim3(Cc/128, ROWS/128), 256, MM_SMEM>>>(
        mlph, mlpl, wfc2_h, wfc2_l, b_fc2, x2, out, nullptr, nullptr, Cc, MLPD, 0);
}